// round 11
// baseline (speedup 1.0000x reference)
#include <cuda_runtime.h>
#include <cuda_bf16.h>
#include <cuda_fp16.h>
#include <math_constants.h>

// ---------------------------------------------------------------------------
//   x [512,4,10,2] i32 -> nonzero list
//   conv1 7x7 s2 p3 4->32 FUSED with pool1 3x3 s2 + bias + relu, per-tile in
//     smem (no global c1!) -> packed padded fp16 pairs g_p1p (35x35 halo)
//   conv2 5x5 s1 p2 32->64 + relu (fp16 mma) -> c2 fp16 NHWC
//   pool2 2x2 s2 -> packed padded pairs (conv3 sIn layout, 17x17) g_p2p
//   conv3 3x3 s1 p1 64->128 + relu (fp16 mma) -> c3 fp16
//   pool 2x2 s2 + mean -> avg ; fc 128->128 relu -> 5
//
// Halo borders of g_p1p/g_p2p are NEVER written; they stay zero from CUDA
// zero-init of __device__ globals (interiors fully overwritten each launch).
//
// mma.m16n8k16.f16 fragment maps (g=lane>>2, t=lane&3), f16x2 regs:
//   A: a0=(g,2t:2t+1) a1=(g+8,...) a2=(g,2t+8:2t+9) a3=(g+8,...)
//   B: b0=B[2t:2t+1][g] b1=B[2t+8:2t+9][g]
//   C: c0=(g,2t) c1=(g,2t+1) c2=(g+8,2t) c3=(g+8,2t+1)
// Channel pairs permuted within each 16-ch chunk: (0,4),(1,5),(2,6),(3,7).
// ---------------------------------------------------------------------------

#define NB 512
#define NIMG (NB * 4)

#define P1_STRIDE 22052                 // uints per image (35*35*18, +2 pad)
#define P2_STRIDE 10404                 // uints per image (17*17*36)

__device__ __align__(16) unsigned g_p1p[NB * P1_STRIDE]; // padded packed conv2 input
__device__ __half g_c2h[NB * 961 * 64];                  // fp16 NHWC
__device__ __align__(16) unsigned g_p2p[NB * P2_STRIDE]; // padded packed conv3 input
__device__ __half g_c3h[NB * 225 * 128];                 // fp16
__device__ float  g_avg[NB * 128];
__device__ int            g_nzcnt [NIMG];
__device__ unsigned short g_nzlist[NIMG * 256];
__device__ __align__(16) unsigned g_w2f[25 * 1024];
__device__ __align__(16) unsigned g_w3f[9 * 4096];

__device__ __forceinline__ unsigned packh2(float a, float b) {
    __half2 h = __floats2half2_rn(a, b);
    return *(unsigned*)&h;
}

__device__ __forceinline__ void mma_f16(float& c0, float& c1, float& c2, float& c3,
                                        unsigned a0, unsigned a1, unsigned a2, unsigned a3,
                                        unsigned b0, unsigned b1) {
    asm volatile("mma.sync.aligned.m16n8k16.row.col.f32.f16.f16.f32 "
                 "{%0,%1,%2,%3},{%4,%5,%6,%7},{%8,%9},{%0,%1,%2,%3};"
                 : "+f"(c0), "+f"(c1), "+f"(c2), "+f"(c3)
                 : "r"(a0), "r"(a1), "r"(a2), "r"(a3), "r"(b0), "r"(b1));
}

// ---------------------------------------------------------------------------
// Launch 1: weight pre-pack (conv2 + conv3 fragment order).
// ---------------------------------------------------------------------------
__global__ void k_prep(const float* __restrict__ w2, const float* __restrict__ w3) {
    int i = blockIdx.x * 256 + threadIdx.x;
    if (i < 25600) {
        int i2 = i & 1023, tap = i >> 10;
        int h = i2 & 1, ln = (i2 >> 1) & 31, j = (i2 >> 6) & 7, ks = i2 >> 9;
        int k = ks * 16 + 2 * (ln & 3) + 8 * h;
        int n = j * 8 + (ln >> 2);
        g_w2f[i] = packh2(w2[n * 800 + k * 25 + tap], w2[n * 800 + (k + 1) * 25 + tap]);
    } else if (i < 25600 + 36864) {
        int ii = i - 25600;
        int i2 = ii & 4095, tap = ii >> 12;
        int h = i2 & 1, ln = (i2 >> 1) & 31, j = (i2 >> 6) & 7;
        int ks = (i2 >> 9) & 3, half = i2 >> 11;
        int k = ks * 16 + 2 * (ln & 3) + 8 * h;
        int oc = half * 64 + j * 8 + (ln >> 2);
        g_w3f[ii] = packh2(w3[oc * 576 + k * 9 + tap], w3[oc * 576 + (k + 1) * 9 + tap]);
    }
}

// ---------------------------------------------------------------------------
// Launch 2: rasterize to nonzero lists. p | code<<14; 0=0.5, 1=1.0, 2=-1.0
// ---------------------------------------------------------------------------
__global__ void k_raster(const int* __restrict__ x) {
    int img = blockIdx.x;
    __shared__ int ax[9], ay[9];
    __shared__ int sdX, sloX, shiX, sloY, shiY;
    __shared__ int sCnt;
    __shared__ unsigned short sList[256];
    int tid = threadIdx.x;
    if (tid < 9) {
        int vx = x[img * 20 + tid * 2 + 0];
        int vy = x[img * 20 + tid * 2 + 1];
        ax[tid] = ((vx + 64) % 127 + 127) % 127;
        ay[tid] = ((64 - vy) % 127 + 127) % 127;
    }
    if (tid == 9) {
        int vx = x[img * 20 + 18];
        int vy = x[img * 20 + 19];
        int dX = 64 + vx, dY = 64 - vy;
        sdX = dX;
        sloX = (dX >= 64) ? 64 : dX + 1;
        shiX = (dX >= 64) ? dX - 1 : 64;
        sloY = (dY >= 64) ? 64 : dY + 1;
        shiY = (dY >= 64) ? dY - 1 : 64;
    }
    if (tid == 10) sCnt = 0;
    __syncthreads();
    for (int p = tid; p < 16384; p += blockDim.x) {
        int y = p >> 7, xx = p & 127;
        float val = 0.f;
        if (y == 64 && xx >= sloX && xx <= shiX) val = -1.f;
        if (xx == sdX && y >= sloY && y <= shiY) val = -1.f;
        if (y >= 63 && y <= 65 && xx >= 63 && xx <= 65)
            val = (y == 64 && xx == 64) ? 1.f : 0.5f;
        #pragma unroll
        for (int k = 0; k < 9; k++) {
            int dy = y - ay[k], dx = xx - ax[k];
            if (dy >= -1 && dy <= 1 && dx >= -1 && dx <= 1)
                val = (dy == 0 && dx == 0) ? 1.f : 0.5f;
        }
        if (val != 0.f) {
            int pos = atomicAdd(&sCnt, 1);
            if (pos < 256) {
                int code = (val == 0.5f) ? 0 : ((val == 1.f) ? 1 : 2);
                sList[pos] = (unsigned short)(p | (code << 14));
            }
        }
    }
    __syncthreads();
    int cnt = sCnt < 256 ? sCnt : 256;
    if (tid == 0) g_nzcnt[img] = cnt;
    for (int i = tid; i < cnt; i += blockDim.x)
        g_nzlist[img * 256 + i] = sList[i];
}

// ---------------------------------------------------------------------------
// Launch 3: FUSED conv1 (sparse scatter in smem) + pool1 + bias + relu ->
// packed padded fp16 (conv2 sIn layout). grid (512, 4): 16x16 pool tiles.
// smem: c1 tile 33x33x32 f32 (139392B) + w1 4x49x32 f32 (25088B).
// ---------------------------------------------------------------------------
#define T1_SC1  (33 * 33 * 32)                     // 34848 floats
#define T1_SW   (4 * 49 * 32)                      // 6272 floats
#define C1_SMEM ((T1_SC1 + T1_SW) * 4)             // 164480 B

__global__ __launch_bounds__(256, 1) void k_conv1f(const float* __restrict__ w1,
                                                   const float* __restrict__ b1) {
    extern __shared__ float smem_f[];
    float* sc1 = smem_f;
    float* sW  = smem_f + T1_SC1;
    __shared__ unsigned short sList[1024];
    __shared__ int sCnt[4];
    int b = blockIdx.x, tile = blockIdx.y;
    int py0 = (tile >> 1) * 16, px0 = (tile & 1) * 16;
    int r0 = 2 * py0, c0 = 2 * px0;
    int tid = threadIdx.x;
    int warp = tid >> 5, lane = tid & 31;

    for (int i = tid; i < T1_SC1; i += 256) sc1[i] = 0.f;
    for (int i = tid; i < T1_SW; i += 256) {
        int oc = i & 31; int r = i >> 5;
        int ci = r / 49; int rr = r - ci * 49;
        int ky = rr / 7, kx = rr - ky * 7;
        sW[i] = w1[((oc * 4 + ci) * 7 + ky) * 7 + kx];
    }
    if (tid < 4) sCnt[tid] = g_nzcnt[b * 4 + tid];
    __syncthreads();
    #pragma unroll
    for (int ci = 0; ci < 4; ci++)
        for (int i = tid; i < sCnt[ci]; i += 256)
            sList[ci * 256 + i] = g_nzlist[(b * 4 + ci) * 256 + i];
    __syncthreads();

    // Scatter: warp per entry, lanes = 32 output channels, smem atomics.
    for (int ci = 0; ci < 4; ci++) {
        int cnt = sCnt[ci];
        const float* wci = sW + ci * 49 * 32;
        for (int e = warp; e < cnt; e += 8) {
            int ent = sList[ci * 256 + e];
            int p = ent & 16383, code = ent >> 14;
            float v = (code == 0) ? 0.5f : ((code == 1) ? 1.0f : -1.0f);
            int iy = p >> 7, ix = p & 127;
            int kyp = (iy + 3) & 1, kxp = (ix + 3) & 1;
            for (int ky = kyp; ky < 7; ky += 2) {
                int oy = (iy + 3 - ky) >> 1;
                int ly = oy - r0;
                if ((unsigned)ly >= 33u || (unsigned)oy >= 64u) continue;
                for (int kx = kxp; kx < 7; kx += 2) {
                    int ox = (ix + 3 - kx) >> 1;
                    int lx = ox - c0;
                    if ((unsigned)lx >= 33u || (unsigned)ox >= 64u) continue;
                    atomicAdd(&sc1[(ly * 33 + lx) * 32 + lane],
                              v * wci[(ky * 7 + kx) * 32 + lane]);
                }
            }
        }
    }
    __syncthreads();

    // Pool 3x3 s2 + bias + relu + fp16 pack -> g_p1p interior.
    for (int it = tid; it < 4096; it += 256) {
        int q = it & 15; int lp = it >> 4;
        int lpy = lp >> 4, lpx = lp & 15;
        int py = py0 + lpy, px = px0 + lpx;
        if (py > 30 || px > 30) continue;
        int chunk = q >> 3, qq = q & 7;
        int oc0 = chunk * 16 + 2 * qq;
        int base = (2 * lpy * 33 + 2 * lpx) * 32 + oc0;
        float m0 = -CUDART_INF_F, m1 = -CUDART_INF_F;
        #pragma unroll
        for (int dy = 0; dy < 3; dy++)
            #pragma unroll
            for (int dx = 0; dx < 3; dx++) {
                float2 vv = *(const float2*)&sc1[base + (dy * 33 + dx) * 32];
                m0 = fmaxf(m0, vv.x); m1 = fmaxf(m1, vv.y);
            }
        float2 bb = *(const float2*)&b1[oc0];
        m0 = fmaxf(m0 + bb.x, 0.f); m1 = fmaxf(m1 + bb.y, 0.f);
        int pos = 2 * (qq & 3) + (qq >> 2);
        g_p1p[b * P1_STRIDE + ((py + 2) * 35 + px + 2) * 18 + chunk * 8 + pos] =
            packh2(m0, m1);
    }
}

// ---------------------------------------------------------------------------
// Launch 4 (PROFILED): conv2 fp16 mma. grid (512,2), 8 warps.
// Warp: 64 px x 64 oc. K = 32 ci x 25 taps. Predicate-free mainloop.
// ---------------------------------------------------------------------------
#define C2_WOFF  P1_STRIDE                          // 22052 (16B aligned)
#define C2_WF    (25 * 1024)
#define C2_SMEM  ((C2_WOFF + C2_WF) * 4)            // 190608 B

extern __shared__ unsigned smem_u[];

__global__ __launch_bounds__(256, 1) void k_conv2_mma(const float* __restrict__ b2) {
    unsigned* sIn = smem_u;
    unsigned* wf  = smem_u + C2_WOFF;
    int b = blockIdx.x;
    int tid = threadIdx.x;
    int warp = tid >> 5, lane = tid & 31;
    int g = lane >> 2, t = lane & 3;

    {
        const uint4* ss = (const uint4*)(g_p1p + (size_t)b * P1_STRIDE);
        uint4* sd = (uint4*)sIn;
        for (int i = tid; i < P1_STRIDE / 4; i += 256) sd[i] = ss[i];
        const uint4* ws = (const uint4*)g_w2f;
        uint4* wd = (uint4*)wf;
        for (int i = tid; i < C2_WF / 4; i += 256) wd[i] = ws[i];
    }
    __syncthreads();

    int p0 = blockIdx.y * 512 + warp * 64;
    int prow[8], abase[8];
    #pragma unroll
    for (int mt = 0; mt < 4; mt++)
        #pragma unroll
        for (int h = 0; h < 2; h++) {
            int i = mt * 2 + h;
            int p = p0 + mt * 16 + g + h * 8;
            int py = p / 31, px = p - py * 31;
            prow[i] = p;
            abase[i] = (py * 35 + px) * 18 + 2 * t;
        }

    float acc[4][8][4];
    #pragma unroll
    for (int mt = 0; mt < 4; mt++)
        #pragma unroll
        for (int j = 0; j < 8; j++)
            #pragma unroll
            for (int q = 0; q < 4; q++) acc[mt][j][q] = 0.f;

    #pragma unroll 1
    for (int tap = 0; tap < 25; tap++) {
        const unsigned* cur = wf + tap * 1024;
        int ky = tap / 5, kx = tap - ky * 5;
        int toff = (ky * 35 + kx) * 18;
        #pragma unroll
        for (int ks = 0; ks < 2; ks++) {
            int k0 = ks * 8;
            uint2 B[8];
            #pragma unroll
            for (int j = 0; j < 8; j++)
                B[j] = *(const uint2*)&cur[((ks * 8 + j) * 32 + lane) * 2];
            #pragma unroll
            for (int mt = 0; mt < 4; mt++) {
                uint2 A0 = *(const uint2*)&sIn[abase[2 * mt] + toff + k0];
                uint2 A1 = *(const uint2*)&sIn[abase[2 * mt + 1] + toff + k0];
                #pragma unroll
                for (int j = 0; j < 8; j++)
                    mma_f16(acc[mt][j][0], acc[mt][j][1], acc[mt][j][2], acc[mt][j][3],
                            A0.x, A1.x, A0.y, A1.y, B[j].x, B[j].y);
            }
        }
    }

    #pragma unroll
    for (int j = 0; j < 8; j++) {
        int oc = j * 8 + 2 * t;
        float2 bb = *(const float2*)&b2[oc];
        #pragma unroll
        for (int mt = 0; mt < 4; mt++) {
            int plo = prow[mt * 2], phi = prow[mt * 2 + 1];
            if (plo < 961)
                *(unsigned*)&g_c2h[((size_t)b * 961 + plo) * 64 + oc] =
                    packh2(fmaxf(acc[mt][j][0] + bb.x, 0.f),
                           fmaxf(acc[mt][j][1] + bb.y, 0.f));
            if (phi < 961)
                *(unsigned*)&g_c2h[((size_t)b * 961 + phi) * 64 + oc] =
                    packh2(fmaxf(acc[mt][j][2] + bb.x, 0.f),
                           fmaxf(acc[mt][j][3] + bb.y, 0.f));
        }
    }
}

// ---------------------------------------------------------------------------
// Launch 5: pool2 2x2 s2 -> packed padded pairs (conv3 layout, 17x17).
// ---------------------------------------------------------------------------
__global__ void k_pool2() {
    int idx = blockIdx.x * 256 + threadIdx.x;     // 512*225*32
    int q = idx & 31; int t2 = idx >> 5;
    int p = t2 % 225; int b = t2 / 225;
    int py = p / 15, px = p - py * 15;
    const __half2* ip = (const __half2*)(g_c2h + ((size_t)(b * 31 + 2 * py) * 31 + 2 * px) * 64 + 2 * q);
    __half2 m = __hmax2(__hmax2(ip[0], ip[32]), __hmax2(ip[31 * 32], ip[32 * 32]));
    int chunk = q >> 3, qq = q & 7;
    int pos = 2 * (qq & 3) + (qq >> 2);
    g_p2p[b * P2_STRIDE + ((py + 1) * 17 + px + 1) * 36 + chunk * 8 + pos] = *(unsigned*)&m;
}

// ---------------------------------------------------------------------------
// Launch 6: conv3 fp16 mma. grid (512), 8 warps. Pure-copy staging,
// predicate-free mainloop. sIn padded 17x17, stride 36.
// ---------------------------------------------------------------------------
#define C3_WOFF  P2_STRIDE                          // 10404 (16B-mult)
#define C3_WF    (9 * 4096)
#define C3_SMEM  ((C3_WOFF + C3_WF) * 4)            // 188472 B

__global__ __launch_bounds__(256, 1) void k_conv3_mma(const float* __restrict__ b3) {
    unsigned* sIn = smem_u;
    unsigned* wf  = smem_u + C3_WOFF;
    int b = blockIdx.x;
    int tid = threadIdx.x;
    int warp = tid >> 5, lane = tid & 31;
    int g = lane >> 2, t = lane & 3;

    {
        const uint4* ss = (const uint4*)(g_p2p + (size_t)b * P2_STRIDE);
        uint4* sd = (uint4*)sIn;
        for (int i = tid; i < P2_STRIDE / 4; i += 256) sd[i] = ss[i];
        const uint4* ws = (const uint4*)g_w3f;
        uint4* wd = (uint4*)wf;
        for (int i = tid; i < C3_WF / 4; i += 256) wd[i] = ws[i];
    }
    __syncthreads();

    int p0 = (warp & 3) * 64;
    int ochalf = warp >> 2;
    int prow[8], abase[8];
    #pragma unroll
    for (int mt = 0; mt < 4; mt++)
        #pragma unroll
        for (int h = 0; h < 2; h++) {
            int i = mt * 2 + h;
            int p = p0 + mt * 16 + g + h * 8;
            int py = p / 15, px = p - py * 15;
            prow[i] = p;
            abase[i] = (py * 17 + px) * 36 + 2 * t;
        }

    float acc[4][8][4];
    #pragma unroll
    for (int mt = 0; mt < 4; mt++)
        #pragma unroll
        for (int j = 0; j < 8; j++)
            #pragma unroll
            for (int q = 0; q < 4; q++) acc[mt][j][q] = 0.f;

    #pragma unroll 1
    for (int tap = 0; tap < 9; tap++) {
        const unsigned* cur = wf + tap * 4096 + ochalf * 2048;
        int ky = tap / 3, kx = tap - ky * 3;
        int toff = (ky * 17 + kx) * 36;
        #pragma unroll
        for (int ks = 0; ks < 4; ks++) {
            int k0 = ks * 8;
            uint2 B[8];
            #pragma unroll
            for (int j = 0; j < 8; j++)
                B[j] = *(const uint2*)&cur[((ks * 8 + j) * 32 + lane) * 2];
            #pragma unroll
            for (int mt = 0; mt < 4; mt++) {
                uint2 A0 = *(const uint2*)&sIn[abase[2 * mt] + toff + k0];
                uint2 A1 = *(const uint2*)&sIn[abase[2 * mt + 1] + toff + k0];
                #pragma unroll
                for (int j = 0; j < 8; j++)
                    mma_f16(acc[mt][j][0], acc[mt][j][1], acc[mt][j][2], acc[mt][j][3],
                            A0.x, A1.x, A0.y, A1.y, B[j].x, B[j].y);
            }
        }
    }

    #pragma unroll
    for (int j = 0; j < 8; j++) {
        int oc = ochalf * 64 + j * 8 + 2 * t;
        float2 bb = *(const float2*)&b3[oc];
        #pragma unroll
        for (int mt = 0; mt < 4; mt++) {
            int plo = prow[mt * 2], phi = prow[mt * 2 + 1];
            if (plo < 225)
                *(unsigned*)&g_c3h[((size_t)b * 225 + plo) * 128 + oc] =
                    packh2(fmaxf(acc[mt][j][0] + bb.x, 0.f),
                           fmaxf(acc[mt][j][1] + bb.y, 0.f));
            if (phi < 225)
                *(unsigned*)&g_c3h[((size_t)b * 225 + phi) * 128 + oc] =
                    packh2(fmaxf(acc[mt][j][2] + bb.x, 0.f),
                           fmaxf(acc[mt][j][3] + bb.y, 0.f));
        }
    }
}

// ---------------------------------------------------------------------------
// Launch 7: pool3 (2x2 s2) + mean.  Launch 8: FC.
// ---------------------------------------------------------------------------
__global__ void k_avg() {
    int idx = blockIdx.x * 256 + threadIdx.x;   // 512*64 pairs
    int q = idx & 63; int b = idx >> 6;
    const __half2* ip = (const __half2*)(g_c3h + (size_t)b * 225 * 128 + 2 * q);
    float s0 = 0.f, s1 = 0.f;
    #pragma unroll
    for (int py = 0; py < 7; py++)
        #pragma unroll
        for (int px = 0; px < 7; px++) {
            const __half2* w = ip + ((2 * py) * 15 + 2 * px) * 64;
            __half2 m = __hmax2(__hmax2(w[0], w[64]), __hmax2(w[15 * 64], w[16 * 64]));
            float2 f = __half22float2(m);
            s0 += f.x; s1 += f.y;
        }
    g_avg[b * 128 + 2 * q]     = s0 * (1.f / 49.f);
    g_avg[b * 128 + 2 * q + 1] = s1 * (1.f / 49.f);
}

__global__ void k_fc(const float* __restrict__ fw1, const float* __restrict__ fb1,
                     const float* __restrict__ fw2, const float* __restrict__ fb2,
                     float* __restrict__ out) {
    int b = blockIdx.x;
    int tid = threadIdx.x;
    __shared__ float sa[128], sh[128];
    sa[tid] = g_avg[b * 128 + tid];
    __syncthreads();
    float s = fb1[tid];
    const float* wr = fw1 + tid * 128;
    #pragma unroll 8
    for (int j = 0; j < 128; j++) s += wr[j] * sa[j];
    sh[tid] = s > 0.f ? s : 0.f;
    __syncthreads();
    if (tid < 5) {
        float o = fb2[tid];
        const float* wr2 = fw2 + tid * 128;
        #pragma unroll 8
        for (int j = 0; j < 128; j++) o += wr2[j] * sh[j];
        out[b * 5 + tid] = o;
    }
}

// ---------------------------------------------------------------------------
extern "C" void kernel_launch(void* const* d_in, const int* in_sizes, int n_in,
                              void* d_out, int out_size) {
    const int*   x   = (const int*)  d_in[0];
    const float* w1  = (const float*)d_in[1];
    const float* b1  = (const float*)d_in[2];
    const float* w2  = (const float*)d_in[3];
    const float* b2  = (const float*)d_in[4];
    const float* w3  = (const float*)d_in[5];
    const float* b3  = (const float*)d_in[6];
    const float* fw1 = (const float*)d_in[7];
    const float* fb1 = (const float*)d_in[8];
    const float* fw2 = (const float*)d_in[9];
    const float* fb2 = (const float*)d_in[10];
    float* out = (float*)d_out;

    cudaFuncSetAttribute(k_conv1f,    cudaFuncAttributeMaxDynamicSharedMemorySize, C1_SMEM);
    cudaFuncSetAttribute(k_conv2_mma, cudaFuncAttributeMaxDynamicSharedMemorySize, C2_SMEM);
    cudaFuncSetAttribute(k_conv3_mma, cudaFuncAttributeMaxDynamicSharedMemorySize, C3_SMEM);

    k_prep<<<(25600 + 36864 + 255) / 256, 256>>>(w2, w3);       // 1
    k_raster<<<NIMG, 256>>>(x);                                 // 2
    k_conv1f<<<dim3(NB, 4), 256, C1_SMEM>>>(w1, b1);            // 3
    k_conv2_mma<<<dim3(NB, 2), 256, C2_SMEM>>>(b2);             // 4 <- profiled
    k_pool2<<<(NB * 225 * 32) / 256, 256>>>();                  // 5
    k_conv3_mma<<<NB, 256, C3_SMEM>>>(b3);                      // 6
    k_avg<<<(NB * 64) / 256, 256>>>();                          // 7
    k_fc<<<NB, 128>>>(fw1, fb1, fw2, fb2, out);                 // 8
}

// round 12
// speedup vs baseline: 1.7295x; 1.7295x over previous
#include <cuda_runtime.h>
#include <cuda_bf16.h>
#include <cuda_fp16.h>
#include <math_constants.h>

// ---------------------------------------------------------------------------
//   x -> nonzero list ; conv1 sparse scatter into c1 f32 NHWC (global)
//   pool1 3x3 s2 + bias + relu -> g_p1p packed padded fp16 (conv2 sIn layout)
//   conv2 5x5 32->64 fp16 mma -> c2 fp16 ; pool2 -> g_p2p packed padded
//   conv3 3x3 64->128 fp16 mma -> c3 fp16 ; pool+mean ; fc
//
// Packed pair layouts (uint = f16x2 of channels 2P,2P+1):
//  conv2 input (32ch, 16 pairs/px, pixel stride 16 uints):
//    pos(P) = 4*(P&3) + (P>>2)   -> thread t LDS.128 at 4t gives pairs
//    {t, t+4, 8+t, 12+t} = k-chunks 0 and 1 for mma thread t.
//  conv3 input (64ch, 32 pairs/px, stride 32): pos(P) = (P&16) + 4*(P&3) + ((P>>2)&3)
//  B weights: uint4 per lane = {B[2jp].b0,b1, B[2jp+1].b0,b1}.
// Halo borders of g_p1p/g_p2p are never written; they stay zero (zero-init).
//
// mma.m16n8k16.f16 (g=lane>>2, t=lane&3): A a0=(g,2t:2t+1) a1=(g+8,..)
//   a2=(g,2t+8:2t+9) a3=(g+8,..); B b0=B[2t:2t+1][g] b1=B[2t+8:2t+9][g];
//   C c0=(g,2t) c1=(g,2t+1) c2=(g+8,2t) c3=(g+8,2t+1)
// ---------------------------------------------------------------------------

#define NB 512
#define NIMG (NB * 4)

#define P1_STRIDE (35 * 35 * 16)        // 19600 uints per image
#define P2_STRIDE (17 * 17 * 32)        // 9248 uints per image

__device__ float  g_c1 [NB * 64 * 64 * 32];              // f32 NHWC (atomics)
__device__ __align__(16) unsigned g_p1p[NB * P1_STRIDE];
__device__ __half g_c2h[NB * 961 * 64];
__device__ __align__(16) unsigned g_p2p[NB * P2_STRIDE];
__device__ __half g_c3h[NB * 225 * 128];
__device__ float  g_avg[NB * 128];
__device__ int            g_nzcnt [NIMG];
__device__ unsigned short g_nzlist[NIMG * 256];
__device__ __align__(16) unsigned g_w2f[25 * 1024];
__device__ __align__(16) unsigned g_w3f[9 * 4096];

__device__ __forceinline__ unsigned packh2(float a, float b) {
    __half2 h = __floats2half2_rn(a, b);
    return *(unsigned*)&h;
}

__device__ __forceinline__ void mma_f16(float& c0, float& c1, float& c2, float& c3,
                                        unsigned a0, unsigned a1, unsigned a2, unsigned a3,
                                        unsigned b0, unsigned b1) {
    asm volatile("mma.sync.aligned.m16n8k16.row.col.f32.f16.f16.f32 "
                 "{%0,%1,%2,%3},{%4,%5,%6,%7},{%8,%9},{%0,%1,%2,%3};"
                 : "+f"(c0), "+f"(c1), "+f"(c2), "+f"(c3)
                 : "r"(a0), "r"(a1), "r"(a2), "r"(a3), "r"(b0), "r"(b1));
}

// ---------------------------------------------------------------------------
// Launch 1: raster (blocks < NIMG) + zero c1 + weight prep, one grid.
// ---------------------------------------------------------------------------
#define ZB1 65536
#define PB  ((25600 + 36864 + 255) / 256)          // 245
#define L1_GRID (NIMG + ZB1 + PB)

__global__ void k_setup(const int* __restrict__ x,
                        const float* __restrict__ w2, const float* __restrict__ w3) {
    int bi = blockIdx.x;
    int tid = threadIdx.x;
    if (bi >= NIMG) {
        int zb = bi - NIMG;
        if (zb < ZB1) {
            ((float4*)g_c1)[zb * 256 + tid] = make_float4(0.f, 0.f, 0.f, 0.f);
        } else {
            int i = (zb - ZB1) * 256 + tid;
            if (i < 25600) {
                int i2 = i & 1023, tap = i >> 10;
                int c = i2 & 3, ln = (i2 >> 2) & 31, jp = (i2 >> 7) & 3, ks = i2 >> 9;
                int h = c & 1, jpar = c >> 1;
                int tt = ln & 3, gg = ln >> 2;
                int k = ks * 16 + 2 * tt + 8 * h;
                int n = (2 * jp + jpar) * 8 + gg;
                g_w2f[i] = packh2(w2[n * 800 + k * 25 + tap],
                                  w2[n * 800 + (k + 1) * 25 + tap]);
            } else if (i < 25600 + 36864) {
                int ii = i - 25600;
                int i2 = ii & 4095, tap = ii >> 12;
                int c = i2 & 3, ln = (i2 >> 2) & 31, jp = (i2 >> 7) & 3;
                int ks = (i2 >> 9) & 3, half = i2 >> 11;
                int h = c & 1, jpar = c >> 1;
                int tt = ln & 3, gg = ln >> 2;
                int k = ks * 16 + 2 * tt + 8 * h;
                int oc = half * 64 + (2 * jp + jpar) * 8 + gg;
                g_w3f[ii] = packh2(w3[oc * 576 + k * 9 + tap],
                                   w3[oc * 576 + (k + 1) * 9 + tap]);
            }
        }
        return;
    }
    int img = bi;
    __shared__ int ax[9], ay[9];
    __shared__ int sdX, sloX, shiX, sloY, shiY;
    __shared__ int sCnt;
    __shared__ unsigned short sList[256];
    if (tid < 9) {
        int vx = x[img * 20 + tid * 2 + 0];
        int vy = x[img * 20 + tid * 2 + 1];
        ax[tid] = ((vx + 64) % 127 + 127) % 127;
        ay[tid] = ((64 - vy) % 127 + 127) % 127;
    }
    if (tid == 9) {
        int vx = x[img * 20 + 18];
        int vy = x[img * 20 + 19];
        int dX = 64 + vx, dY = 64 - vy;
        sdX = dX;
        sloX = (dX >= 64) ? 64 : dX + 1;
        shiX = (dX >= 64) ? dX - 1 : 64;
        sloY = (dY >= 64) ? 64 : dY + 1;
        shiY = (dY >= 64) ? dY - 1 : 64;
    }
    if (tid == 10) sCnt = 0;
    __syncthreads();
    for (int p = tid; p < 16384; p += blockDim.x) {
        int y = p >> 7, xx = p & 127;
        float val = 0.f;
        if (y == 64 && xx >= sloX && xx <= shiX) val = -1.f;
        if (xx == sdX && y >= sloY && y <= shiY) val = -1.f;
        if (y >= 63 && y <= 65 && xx >= 63 && xx <= 65)
            val = (y == 64 && xx == 64) ? 1.f : 0.5f;
        #pragma unroll
        for (int k = 0; k < 9; k++) {
            int dy = y - ay[k], dx = xx - ax[k];
            if (dy >= -1 && dy <= 1 && dx >= -1 && dx <= 1)
                val = (dy == 0 && dx == 0) ? 1.f : 0.5f;
        }
        if (val != 0.f) {
            int pos = atomicAdd(&sCnt, 1);
            if (pos < 256) {
                int code = (val == 0.5f) ? 0 : ((val == 1.f) ? 1 : 2);
                sList[pos] = (unsigned short)(p | (code << 14));
            }
        }
    }
    __syncthreads();
    int cnt = sCnt < 256 ? sCnt : 256;
    if (tid == 0) g_nzcnt[img] = cnt;
    for (int i = tid; i < cnt; i += blockDim.x)
        g_nzlist[img * 256 + i] = sList[i];
}

// ---------------------------------------------------------------------------
// Launch 2: sparse conv1 scatter (f32 atomics into NHWC c1).
// ---------------------------------------------------------------------------
__global__ void k_scatter1(const float* __restrict__ w1) {
    int img = blockIdx.x;
    int b = img >> 2, ci = img & 3;
    __shared__ float sW[49 * 32];
    __shared__ unsigned short sList[256];
    __shared__ int sCnt;
    int tid = threadIdx.x;
    for (int i = tid; i < 49 * 32; i += 256) {
        int oc = i & 31; int r = i >> 5;
        int ky = r / 7, kx = r % 7;
        sW[i] = w1[((oc * 4 + ci) * 7 + ky) * 7 + kx];
    }
    if (tid == 0) sCnt = g_nzcnt[img];
    __syncthreads();
    int cnt = sCnt;
    for (int i = tid; i < cnt; i += 256) sList[i] = g_nzlist[img * 256 + i];
    __syncthreads();
    int warp = tid >> 5, lane = tid & 31;
    for (int e = warp; e < cnt; e += 8) {
        int ent = sList[e];
        int p = ent & 16383, code = ent >> 14;
        float v = (code == 0) ? 0.5f : ((code == 1) ? 1.0f : -1.0f);
        int iy = p >> 7, ix = p & 127;
        #pragma unroll
        for (int ky = 0; ky < 7; ky++) {
            int t = iy + 3 - ky;
            if (t < 0 || t >= 128 || (t & 1)) continue;
            int oy = t >> 1;
            #pragma unroll
            for (int kx = 0; kx < 7; kx++) {
                int u = ix + 3 - kx;
                if (u < 0 || u >= 128 || (u & 1)) continue;
                int ox = u >> 1;
                atomicAdd(&g_c1[((b * 64 + oy) * 64 + ox) * 32 + lane],
                          v * sW[(ky * 7 + kx) * 32 + lane]);
            }
        }
    }
}

// ---------------------------------------------------------------------------
// Launch 3: pool1 3x3 s2 + bias + relu -> packed padded fp16 (conv2 layout).
// idx over 512*961*16 pairs. pair index u, pos = 4*(u&3)+(u>>2).
// ---------------------------------------------------------------------------
__global__ void k_pool1(const float* __restrict__ b1) {
    int idx = blockIdx.x * 256 + threadIdx.x;
    int u = idx & 15; int t2 = idx >> 4;
    int p = t2 % 961; int b = t2 / 961;
    int py = p / 31, px = p - py * 31;
    int oc0 = 2 * u;
    const float* ip = g_c1 + ((size_t)(b * 64 + 2 * py) * 64 + 2 * px) * 32 + oc0;
    float m0 = -CUDART_INF_F, m1 = -CUDART_INF_F;
    #pragma unroll
    for (int dy = 0; dy < 3; dy++)
        #pragma unroll
        for (int dx = 0; dx < 3; dx++) {
            float2 v = *(const float2*)&ip[(dy * 64 + dx) * 32];
            m0 = fmaxf(m0, v.x); m1 = fmaxf(m1, v.y);
        }
    float2 bb = *(const float2*)&b1[oc0];
    m0 = fmaxf(m0 + bb.x, 0.f); m1 = fmaxf(m1 + bb.y, 0.f);
    int pos = 4 * (u & 3) + (u >> 2);
    g_p1p[b * P1_STRIDE + ((py + 2) * 35 + px + 2) * 16 + pos] = packh2(m0, m1);
}

// ---------------------------------------------------------------------------
// Launch 4 (PROFILED): conv2 fp16 mma. grid (512,2), 8 warps.
// Warp: 64 px x 64 oc. K = 32 ci x 25 taps. LDS.128 A+B, no predicates.
// ---------------------------------------------------------------------------
#define C2_WOFF  P1_STRIDE                          // 19600 (16B-mult)
#define C2_WF    (25 * 1024)
#define C2_SMEM  ((C2_WOFF + C2_WF) * 4)            // 180800 B

extern __shared__ unsigned smem_u[];

__global__ __launch_bounds__(256, 1) void k_conv2_mma(const float* __restrict__ b2) {
    unsigned* sIn = smem_u;
    unsigned* wf  = smem_u + C2_WOFF;
    int b = blockIdx.x;
    int tid = threadIdx.x;
    int warp = tid >> 5, lane = tid & 31;
    int g = lane >> 2, t = lane & 3;

    {
        const uint4* ss = (const uint4*)(g_p1p + (size_t)b * P1_STRIDE);
        uint4* sd = (uint4*)sIn;
        for (int i = tid; i < P1_STRIDE / 4; i += 256) sd[i] = ss[i];
        const uint4* ws = (const uint4*)g_w2f;
        uint4* wd = (uint4*)wf;
        for (int i = tid; i < C2_WF / 4; i += 256) wd[i] = ws[i];
    }
    __syncthreads();

    int p0 = blockIdx.y * 512 + warp * 64;
    int prow[8], abase[8];
    #pragma unroll
    for (int mt = 0; mt < 4; mt++)
        #pragma unroll
        for (int h = 0; h < 2; h++) {
            int i = mt * 2 + h;
            int p = p0 + mt * 16 + g + h * 8;
            int py = p / 31, px = p - py * 31;
            prow[i] = p;
            abase[i] = (py * 35 + px) * 16 + 4 * t;
        }

    float acc[4][8][4];
    #pragma unroll
    for (int mt = 0; mt < 4; mt++)
        #pragma unroll
        for (int j = 0; j < 8; j++)
            #pragma unroll
            for (int q = 0; q < 4; q++) acc[mt][j][q] = 0.f;

    #pragma unroll 1
    for (int tap = 0; tap < 25; tap++) {
        const unsigned* cur = wf + tap * 1024;
        int ky = tap / 5, kx = tap - ky * 5;
        int toff = (ky * 35 + kx) * 16;
        uint4 Ar[8];
        #pragma unroll
        for (int i = 0; i < 8; i++)
            Ar[i] = *(const uint4*)&sIn[abase[i] + toff];
        #pragma unroll
        for (int ks = 0; ks < 2; ks++) {
            uint4 Bq[4];
            #pragma unroll
            for (int jp = 0; jp < 4; jp++)
                Bq[jp] = *(const uint4*)&cur[((ks * 4 + jp) * 32 + lane) * 4];
            #pragma unroll
            for (int mt = 0; mt < 4; mt++) {
                unsigned a0 = ks ? Ar[2 * mt].z     : Ar[2 * mt].x;
                unsigned a2 = ks ? Ar[2 * mt].w     : Ar[2 * mt].y;
                unsigned a1 = ks ? Ar[2 * mt + 1].z : Ar[2 * mt + 1].x;
                unsigned a3 = ks ? Ar[2 * mt + 1].w : Ar[2 * mt + 1].y;
                #pragma unroll
                for (int jp = 0; jp < 4; jp++) {
                    mma_f16(acc[mt][2 * jp][0], acc[mt][2 * jp][1],
                            acc[mt][2 * jp][2], acc[mt][2 * jp][3],
                            a0, a1, a2, a3, Bq[jp].x, Bq[jp].y);
                    mma_f16(acc[mt][2 * jp + 1][0], acc[mt][2 * jp + 1][1],
                            acc[mt][2 * jp + 1][2], acc[mt][2 * jp + 1][3],
                            a0, a1, a2, a3, Bq[jp].z, Bq[jp].w);
                }
            }
        }
    }

    #pragma unroll
    for (int j = 0; j < 8; j++) {
        int oc = j * 8 + 2 * t;
        float2 bb = *(const float2*)&b2[oc];
        #pragma unroll
        for (int mt = 0; mt < 4; mt++) {
            int plo = prow[mt * 2], phi = prow[mt * 2 + 1];
            if (plo < 961)
                *(unsigned*)&g_c2h[((size_t)b * 961 + plo) * 64 + oc] =
                    packh2(fmaxf(acc[mt][j][0] + bb.x, 0.f),
                           fmaxf(acc[mt][j][1] + bb.y, 0.f));
            if (phi < 961)
                *(unsigned*)&g_c2h[((size_t)b * 961 + phi) * 64 + oc] =
                    packh2(fmaxf(acc[mt][j][2] + bb.x, 0.f),
                           fmaxf(acc[mt][j][3] + bb.y, 0.f));
        }
    }
}

// ---------------------------------------------------------------------------
// Launch 5: pool2 2x2 s2 -> packed padded pairs (conv3 layout, 17x17).
// pair q, pos = (q&16) + 4*(q&3) + ((q>>2)&3). Pixel stride 32 uints.
// ---------------------------------------------------------------------------
__global__ void k_pool2() {
    int idx = blockIdx.x * 256 + threadIdx.x;     // 512*225*32
    int q = idx & 31; int t2 = idx >> 5;
    int p = t2 % 225; int b = t2 / 225;
    int py = p / 15, px = p - py * 15;
    const __half2* ip = (const __half2*)(g_c2h + ((size_t)(b * 31 + 2 * py) * 31 + 2 * px) * 64 + 2 * q);
    __half2 m = __hmax2(__hmax2(ip[0], ip[32]), __hmax2(ip[31 * 32], ip[32 * 32]));
    int pos = (q & 16) + 4 * (q & 3) + ((q >> 2) & 3);
    g_p2p[b * P2_STRIDE + ((py + 1) * 17 + px + 1) * 32 + pos] = *(unsigned*)&m;
}

// ---------------------------------------------------------------------------
// Launch 6: conv3 fp16 mma. grid (512), 8 warps. LDS.128 A+B.
// sIn padded 17x17, stride 32 uints.
// ---------------------------------------------------------------------------
#define C3_WOFF  P2_STRIDE                          // 9248 (16B-mult)
#define C3_WF    (9 * 4096)
#define C3_SMEM  ((C3_WOFF + C3_WF) * 4)            // 184448 B

__global__ __launch_bounds__(256, 1) void k_conv3_mma(const float* __restrict__ b3) {
    unsigned* sIn = smem_u;
    unsigned* wf  = smem_u + C3_WOFF;
    int b = blockIdx.x;
    int tid = threadIdx.x;
    int warp = tid >> 5, lane = tid & 31;
    int g = lane >> 2, t = lane & 3;

    {
        const uint4* ss = (const uint4*)(g_p2p + (size_t)b * P2_STRIDE);
        uint4* sd = (uint4*)sIn;
        for (int i = tid; i < P2_STRIDE / 4; i += 256) sd[i] = ss[i];
        const uint4* ws = (const uint4*)g_w3f;
        uint4* wd = (uint4*)wf;
        for (int i = tid; i < C3_WF / 4; i += 256) wd[i] = ws[i];
    }
    __syncthreads();

    int p0 = (warp & 3) * 64;
    int ochalf = warp >> 2;
    int prow[8], abase[8];
    #pragma unroll
    for (int mt = 0; mt < 4; mt++)
        #pragma unroll
        for (int h = 0; h < 2; h++) {
            int i = mt * 2 + h;
            int p = p0 + mt * 16 + g + h * 8;
            int py = p / 15, px = p - py * 15;
            prow[i] = p;
            abase[i] = (py * 17 + px) * 32 + 4 * t;
        }

    float acc[4][8][4];
    #pragma unroll
    for (int mt = 0; mt < 4; mt++)
        #pragma unroll
        for (int j = 0; j < 8; j++)
            #pragma unroll
            for (int q = 0; q < 4; q++) acc[mt][j][q] = 0.f;

    #pragma unroll 1
    for (int tap = 0; tap < 9; tap++) {
        const unsigned* cur = wf + tap * 4096 + ochalf * 2048;
        int ky = tap / 3, kx = tap - ky * 3;
        int toff = (ky * 17 + kx) * 32;
        #pragma unroll
        for (int kk = 0; kk < 2; kk++) {           // channel-half: ks pair
            uint4 Ar[8];
            #pragma unroll
            for (int i = 0; i < 8; i++)
                Ar[i] = *(const uint4*)&sIn[abase[i] + toff + 16 * kk];
            #pragma unroll
            for (int ks2 = 0; ks2 < 2; ks2++) {
                int ks = kk * 2 + ks2;
                uint4 Bq[4];
                #pragma unroll
                for (int jp = 0; jp < 4; jp++)
                    Bq[jp] = *(const uint4*)&cur[((ks * 4 + jp) * 32 + lane) * 4];
                #pragma unroll
                for (int mt = 0; mt < 4; mt++) {
                    unsigned a0 = ks2 ? Ar[2 * mt].z     : Ar[2 * mt].x;
                    unsigned a2 = ks2 ? Ar[2 * mt].w     : Ar[2 * mt].y;
                    unsigned a1 = ks2 ? Ar[2 * mt + 1].z : Ar[2 * mt + 1].x;
                    unsigned a3 = ks2 ? Ar[2 * mt + 1].w : Ar[2 * mt + 1].y;
                    #pragma unroll
                    for (int jp = 0; jp < 4; jp++) {
                        mma_f16(acc[mt][2 * jp][0], acc[mt][2 * jp][1],
                                acc[mt][2 * jp][2], acc[mt][2 * jp][3],
                                a0, a1, a2, a3, Bq[jp].x, Bq[jp].y);
                        mma_f16(acc[mt][2 * jp + 1][0], acc[mt][2 * jp + 1][1],
                                acc[mt][2 * jp + 1][2], acc[mt][2 * jp + 1][3],
                                a0, a1, a2, a3, Bq[jp].z, Bq[jp].w);
                    }
                }
            }
        }
    }

    #pragma unroll
    for (int j = 0; j < 8; j++) {
        int oc = ochalf * 64 + j * 8 + 2 * t;
        float2 bb = *(const float2*)&b3[oc];
        #pragma unroll
        for (int mt = 0; mt < 4; mt++) {
            int plo = prow[mt * 2], phi = prow[mt * 2 + 1];
            if (plo < 225)
                *(unsigned*)&g_c3h[((size_t)b * 225 + plo) * 128 + oc] =
                    packh2(fmaxf(acc[mt][j][0] + bb.x, 0.f),
                           fmaxf(acc[mt][j][1] + bb.y, 0.f));
            if (phi < 225)
                *(unsigned*)&g_c3h[((size_t)b * 225 + phi) * 128 + oc] =
                    packh2(fmaxf(acc[mt][j][2] + bb.x, 0.f),
                           fmaxf(acc[mt][j][3] + bb.y, 0.f));
        }
    }
}

// ---------------------------------------------------------------------------
// Launch 7: pool3 (2x2 s2) + mean.  Launch 8: FC.
// ---------------------------------------------------------------------------
__global__ void k_avg() {
    int idx = blockIdx.x * 256 + threadIdx.x;   // 512*64 pairs
    int q = idx & 63; int b = idx >> 6;
    const __half2* ip = (const __half2*)(g_c3h + (size_t)b * 225 * 128 + 2 * q);
    float s0 = 0.f, s1 = 0.f;
    #pragma unroll
    for (int py = 0; py < 7; py++)
        #pragma unroll
        for (int px = 0; px < 7; px++) {
            const __half2* w = ip + ((2 * py) * 15 + 2 * px) * 64;
            __half2 m = __hmax2(__hmax2(w[0], w[64]), __hmax2(w[15 * 64], w[16 * 64]));
            float2 f = __half22float2(m);
            s0 += f.x; s1 += f.y;
        }
    g_avg[b * 128 + 2 * q]     = s0 * (1.f / 49.f);
    g_avg[b * 128 + 2 * q + 1] = s1 * (1.f / 49.f);
}

__global__ void k_fc(const float* __restrict__ fw1, const float* __restrict__ fb1,
                     const float* __restrict__ fw2, const float* __restrict__ fb2,
                     float* __restrict__ out) {
    int b = blockIdx.x;
    int tid = threadIdx.x;
    __shared__ float sa[128], sh[128];
    sa[tid] = g_avg[b * 128 + tid];
    __syncthreads();
    float s = fb1[tid];
    const float* wr = fw1 + tid * 128;
    #pragma unroll 8
    for (int j = 0; j < 128; j++) s += wr[j] * sa[j];
    sh[tid] = s > 0.f ? s : 0.f;
    __syncthreads();
    if (tid < 5) {
        float o = fb2[tid];
        const float* wr2 = fw2 + tid * 128;
        #pragma unroll 8
        for (int j = 0; j < 128; j++) o += wr2[j] * sh[j];
        out[b * 5 + tid] = o;
    }
}

// ---------------------------------------------------------------------------
extern "C" void kernel_launch(void* const* d_in, const int* in_sizes, int n_in,
                              void* d_out, int out_size) {
    const int*   x   = (const int*)  d_in[0];
    const float* w1  = (const float*)d_in[1];
    const float* b1  = (const float*)d_in[2];
    const float* w2  = (const float*)d_in[3];
    const float* b2  = (const float*)d_in[4];
    const float* w3  = (const float*)d_in[5];
    const float* b3  = (const float*)d_in[6];
    const float* fw1 = (const float*)d_in[7];
    const float* fb1 = (const float*)d_in[8];
    const float* fw2 = (const float*)d_in[9];
    const float* fb2 = (const float*)d_in[10];
    float* out = (float*)d_out;

    cudaFuncSetAttribute(k_conv2_mma, cudaFuncAttributeMaxDynamicSharedMemorySize, C2_SMEM);
    cudaFuncSetAttribute(k_conv3_mma, cudaFuncAttributeMaxDynamicSharedMemorySize, C3_SMEM);

    k_setup<<<L1_GRID, 256>>>(x, w2, w3);                       // 1
    k_scatter1<<<NIMG, 256>>>(w1);                              // 2
    k_pool1<<<(NB * 961 * 16) / 256, 256>>>(b1);                // 3
    k_conv2_mma<<<dim3(NB, 2), 256, C2_SMEM>>>(b2);             // 4 <- profiled
    k_pool2<<<(NB * 225 * 32) / 256, 256>>>();                  // 5
    k_conv3_mma<<<NB, 256, C3_SMEM>>>(b3);                      // 6
    k_avg<<<(NB * 64) / 256, 256>>>();                          // 7
    k_fc<<<NB, 128>>>(fw1, fb1, fw2, fb2, out);                 // 8
}

// round 13
// speedup vs baseline: 1.8626x; 1.0770x over previous
#include <cuda_runtime.h>
#include <cuda_bf16.h>
#include <cuda_fp16.h>
#include <math_constants.h>

// ---------------------------------------------------------------------------
//   x -> nonzero list ; conv1 sparse scatter into c1 f32 NHWC (global)
//   pool1 3x3 s2 + bias + relu -> g_p1p packed padded fp16 (conv2 sIn layout)
//   conv2 5x5 32->64 fp16 mma, grid (512, 2 row-halves, 2 oc-halves) -> 2 blk/SM
//   pool2 2x2 s2 -> g_p2p packed padded ; conv3 3x3 64->128, grid (512, 2 oc)
//   pool+mean ; fc
//
// Packed pair layouts (uint = f16x2 of channels 2P,2P+1):
//  conv2 input (32ch, 16 pairs/px, stride 16): pos(P) = 4*(P&3) + (P>>2)
//    -> thread t LDS.128 at 4t gives pairs {t,t+4,8+t,12+t} (k-chunks 0,1).
//  conv3 input (64ch, stride 32): pos(P) = (P&16) + 4*(P&3) + ((P>>2)&3)
//  B weights: uint4 per lane = {B[2jp].b0,b1, B[2jp+1].b0,b1}, per oc-half.
// Halo borders of g_p1p/g_p2p are never written (zero-init persists).
//
// mma.m16n8k16.f16 (g=lane>>2, t=lane&3): A a0=(g,2t:2t+1) a1=(g+8,..)
//   a2=(g,2t+8:2t+9) a3=(g+8,..); B b0=B[2t:2t+1][g] b1=B[2t+8:2t+9][g];
//   C c0=(g,2t) c1=(g,2t+1) c2=(g+8,2t) c3=(g+8,2t+1)
// ---------------------------------------------------------------------------

#define NB 512
#define NIMG (NB * 4)

#define P1_STRIDE (35 * 35 * 16)        // 19600 uints per image
#define P2_STRIDE (17 * 17 * 32)        // 9248 uints per image

__device__ float  g_c1 [NB * 64 * 64 * 32];
__device__ __align__(16) unsigned g_p1p[NB * P1_STRIDE];
__device__ __half g_c2h[NB * 961 * 64];
__device__ __align__(16) unsigned g_p2p[NB * P2_STRIDE];
__device__ __half g_c3h[NB * 225 * 128];
__device__ float  g_avg[NB * 128];
__device__ int            g_nzcnt [NIMG];
__device__ unsigned short g_nzlist[NIMG * 256];
__device__ __align__(16) unsigned g_w2f[2 * 25 * 512];   // [ochalf][tap][512]
__device__ __align__(16) unsigned g_w3f[2 * 9 * 2048];   // [ochalf][tap][2048]

__device__ __forceinline__ unsigned packh2(float a, float b) {
    __half2 h = __floats2half2_rn(a, b);
    return *(unsigned*)&h;
}

__device__ __forceinline__ void mma_f16(float& c0, float& c1, float& c2, float& c3,
                                        unsigned a0, unsigned a1, unsigned a2, unsigned a3,
                                        unsigned b0, unsigned b1) {
    asm volatile("mma.sync.aligned.m16n8k16.row.col.f32.f16.f16.f32 "
                 "{%0,%1,%2,%3},{%4,%5,%6,%7},{%8,%9},{%0,%1,%2,%3};"
                 : "+f"(c0), "+f"(c1), "+f"(c2), "+f"(c3)
                 : "r"(a0), "r"(a1), "r"(a2), "r"(a3), "r"(b0), "r"(b1));
}

// ---------------------------------------------------------------------------
// Launch 1: raster (blocks < NIMG) + zero c1 + weight prep, one grid.
// ---------------------------------------------------------------------------
#define ZB1 65536
#define PB  ((25600 + 36864 + 255) / 256)
#define L1_GRID (NIMG + ZB1 + PB)

__global__ void k_setup(const int* __restrict__ x,
                        const float* __restrict__ w2, const float* __restrict__ w3) {
    int bi = blockIdx.x;
    int tid = threadIdx.x;
    if (bi >= NIMG) {
        int zb = bi - NIMG;
        if (zb < ZB1) {
            ((float4*)g_c1)[zb * 256 + tid] = make_float4(0.f, 0.f, 0.f, 0.f);
        } else {
            int i = (zb - ZB1) * 256 + tid;
            if (i < 25600) {
                int half = i / 12800; int r = i - half * 12800;
                int tap = r >> 9; int i2 = r & 511;
                int c = i2 & 3, ln = (i2 >> 2) & 31, jp = (i2 >> 7) & 1, ks = (i2 >> 8) & 1;
                int h = c & 1, jpar = c >> 1;
                int tt = ln & 3, gg = ln >> 2;
                int k = ks * 16 + 2 * tt + 8 * h;
                int n = half * 32 + (2 * jp + jpar) * 8 + gg;
                g_w2f[i] = packh2(w2[n * 800 + k * 25 + tap],
                                  w2[n * 800 + (k + 1) * 25 + tap]);
            } else if (i < 25600 + 36864) {
                int ii = i - 25600;
                int half = ii / 18432; int r = ii - half * 18432;
                int tap = r >> 11; int i2 = r & 2047;
                int c = i2 & 3, ln = (i2 >> 2) & 31, jp = (i2 >> 7) & 3, ks = (i2 >> 9) & 3;
                int h = c & 1, jpar = c >> 1;
                int tt = ln & 3, gg = ln >> 2;
                int k = ks * 16 + 2 * tt + 8 * h;
                int oc = half * 64 + (2 * jp + jpar) * 8 + gg;
                g_w3f[ii] = packh2(w3[oc * 576 + k * 9 + tap],
                                   w3[oc * 576 + (k + 1) * 9 + tap]);
            }
        }
        return;
    }
    int img = bi;
    __shared__ int ax[9], ay[9];
    __shared__ int sdX, sloX, shiX, sloY, shiY;
    __shared__ int sCnt;
    __shared__ unsigned short sList[256];
    if (tid < 9) {
        int vx = x[img * 20 + tid * 2 + 0];
        int vy = x[img * 20 + tid * 2 + 1];
        ax[tid] = ((vx + 64) % 127 + 127) % 127;
        ay[tid] = ((64 - vy) % 127 + 127) % 127;
    }
    if (tid == 9) {
        int vx = x[img * 20 + 18];
        int vy = x[img * 20 + 19];
        int dX = 64 + vx, dY = 64 - vy;
        sdX = dX;
        sloX = (dX >= 64) ? 64 : dX + 1;
        shiX = (dX >= 64) ? dX - 1 : 64;
        sloY = (dY >= 64) ? 64 : dY + 1;
        shiY = (dY >= 64) ? dY - 1 : 64;
    }
    if (tid == 10) sCnt = 0;
    __syncthreads();
    for (int p = tid; p < 16384; p += blockDim.x) {
        int y = p >> 7, xx = p & 127;
        float val = 0.f;
        if (y == 64 && xx >= sloX && xx <= shiX) val = -1.f;
        if (xx == sdX && y >= sloY && y <= shiY) val = -1.f;
        if (y >= 63 && y <= 65 && xx >= 63 && xx <= 65)
            val = (y == 64 && xx == 64) ? 1.f : 0.5f;
        #pragma unroll
        for (int k = 0; k < 9; k++) {
            int dy = y - ay[k], dx = xx - ax[k];
            if (dy >= -1 && dy <= 1 && dx >= -1 && dx <= 1)
                val = (dy == 0 && dx == 0) ? 1.f : 0.5f;
        }
        if (val != 0.f) {
            int pos = atomicAdd(&sCnt, 1);
            if (pos < 256) {
                int code = (val == 0.5f) ? 0 : ((val == 1.f) ? 1 : 2);
                sList[pos] = (unsigned short)(p | (code << 14));
            }
        }
    }
    __syncthreads();
    int cnt = sCnt < 256 ? sCnt : 256;
    if (tid == 0) g_nzcnt[img] = cnt;
    for (int i = tid; i < cnt; i += blockDim.x)
        g_nzlist[img * 256 + i] = sList[i];
}

// ---------------------------------------------------------------------------
// Launch 2: sparse conv1 scatter (f32 atomics into NHWC c1).
// ---------------------------------------------------------------------------
__global__ void k_scatter1(const float* __restrict__ w1) {
    int img = blockIdx.x;
    int b = img >> 2, ci = img & 3;
    __shared__ float sW[49 * 32];
    __shared__ unsigned short sList[256];
    __shared__ int sCnt;
    int tid = threadIdx.x;
    for (int i = tid; i < 49 * 32; i += 256) {
        int oc = i & 31; int r = i >> 5;
        int ky = r / 7, kx = r % 7;
        sW[i] = w1[((oc * 4 + ci) * 7 + ky) * 7 + kx];
    }
    if (tid == 0) sCnt = g_nzcnt[img];
    __syncthreads();
    int cnt = sCnt;
    for (int i = tid; i < cnt; i += 256) sList[i] = g_nzlist[img * 256 + i];
    __syncthreads();
    int warp = tid >> 5, lane = tid & 31;
    for (int e = warp; e < cnt; e += 8) {
        int ent = sList[e];
        int p = ent & 16383, code = ent >> 14;
        float v = (code == 0) ? 0.5f : ((code == 1) ? 1.0f : -1.0f);
        int iy = p >> 7, ix = p & 127;
        #pragma unroll
        for (int ky = 0; ky < 7; ky++) {
            int t = iy + 3 - ky;
            if (t < 0 || t >= 128 || (t & 1)) continue;
            int oy = t >> 1;
            #pragma unroll
            for (int kx = 0; kx < 7; kx++) {
                int u = ix + 3 - kx;
                if (u < 0 || u >= 128 || (u & 1)) continue;
                int ox = u >> 1;
                atomicAdd(&g_c1[((b * 64 + oy) * 64 + ox) * 32 + lane],
                          v * sW[(ky * 7 + kx) * 32 + lane]);
            }
        }
    }
}

// ---------------------------------------------------------------------------
// Launch 3: pool1 -> packed padded fp16 (conv2 layout). pos = 4*(u&3)+(u>>2).
// ---------------------------------------------------------------------------
__global__ void k_pool1(const float* __restrict__ b1) {
    int idx = blockIdx.x * 256 + threadIdx.x;
    int u = idx & 15; int t2 = idx >> 4;
    int p = t2 % 961; int b = t2 / 961;
    int py = p / 31, px = p - py * 31;
    int oc0 = 2 * u;
    const float* ip = g_c1 + ((size_t)(b * 64 + 2 * py) * 64 + 2 * px) * 32 + oc0;
    float m0 = -CUDART_INF_F, m1 = -CUDART_INF_F;
    #pragma unroll
    for (int dy = 0; dy < 3; dy++)
        #pragma unroll
        for (int dx = 0; dx < 3; dx++) {
            float2 v = *(const float2*)&ip[(dy * 64 + dx) * 32];
            m0 = fmaxf(m0, v.x); m1 = fmaxf(m1, v.y);
        }
    float2 bb = *(const float2*)&b1[oc0];
    m0 = fmaxf(m0 + bb.x, 0.f); m1 = fmaxf(m1 + bb.y, 0.f);
    int pos = 4 * (u & 3) + (u >> 2);
    g_p1p[b * P1_STRIDE + ((py + 2) * 35 + px + 2) * 16 + pos] = packh2(m0, m1);
}

// ---------------------------------------------------------------------------
// Launch 4 (PROFILED): conv2 fp16 mma. grid (512, 2 row-halves, 2 oc-halves).
// 8 warps, each 64 px x 32 oc. sIn = 21 input rows. 2 blocks/SM.
// ---------------------------------------------------------------------------
#define C2_SINU  (21 * 35 * 16)                     // 11760 uints
#define C2_WFU   (25 * 512)                         // 12800 uints
#define C2_SMEM  ((C2_SINU + C2_WFU) * 4)           // 98240 B

extern __shared__ unsigned smem_u[];

__global__ __launch_bounds__(256, 2) void k_conv2_mma(const float* __restrict__ b2) {
    unsigned* sIn = smem_u;
    unsigned* wf  = smem_u + C2_SINU;
    int b = blockIdx.x;
    int y0 = blockIdx.y * 16;
    int ochalf = blockIdx.z;
    int tid = threadIdx.x;
    int warp = tid >> 5, lane = tid & 31;
    int g = lane >> 2, t = lane & 3;

    {
        // copy padded input rows y0 .. y0+20 (rows >= 35 -> zero)
        const uint4* ss = (const uint4*)(g_p1p + (size_t)b * P1_STRIDE + y0 * 35 * 16);
        uint4* sd = (uint4*)sIn;
        int navail = (35 - y0) * 35 * 4;            // uint4 count available
        for (int i = tid; i < C2_SINU / 4; i += 256)
            sd[i] = (i < navail) ? ss[i] : make_uint4(0u, 0u, 0u, 0u);
        const uint4* ws = (const uint4*)(g_w2f + ochalf * C2_WFU);
        uint4* wd = (uint4*)wf;
        for (int i = tid; i < C2_WFU / 4; i += 256) wd[i] = ws[i];
    }
    __syncthreads();

    int p0 = warp * 64;
    int prow[8], abase[8];
    #pragma unroll
    for (int mt = 0; mt < 4; mt++)
        #pragma unroll
        for (int h = 0; h < 2; h++) {
            int i = mt * 2 + h;
            int p = p0 + mt * 16 + g + h * 8;       // 0..511 local
            int pyl = p / 31, px = p - pyl * 31;
            prow[i] = (y0 + pyl) * 31 + px;         // global pixel (>=961 if OOB)
            abase[i] = (pyl * 35 + px) * 16 + 4 * t;
        }

    float acc[4][4][4];
    #pragma unroll
    for (int mt = 0; mt < 4; mt++)
        #pragma unroll
        for (int j = 0; j < 4; j++)
            #pragma unroll
            for (int q = 0; q < 4; q++) acc[mt][j][q] = 0.f;

    #pragma unroll 1
    for (int tap = 0; tap < 25; tap++) {
        const unsigned* cur = wf + tap * 512;
        int ky = tap / 5, kx = tap - ky * 5;
        int toff = (ky * 35 + kx) * 16;
        uint4 Ar[8];
        #pragma unroll
        for (int i = 0; i < 8; i++)
            Ar[i] = *(const uint4*)&sIn[abase[i] + toff];
        #pragma unroll
        for (int ks = 0; ks < 2; ks++) {
            uint4 Bq[2];
            #pragma unroll
            for (int jp = 0; jp < 2; jp++)
                Bq[jp] = *(const uint4*)&cur[((ks * 2 + jp) * 32 + lane) * 4];
            #pragma unroll
            for (int mt = 0; mt < 4; mt++) {
                unsigned a0 = ks ? Ar[2 * mt].z     : Ar[2 * mt].x;
                unsigned a2 = ks ? Ar[2 * mt].w     : Ar[2 * mt].y;
                unsigned a1 = ks ? Ar[2 * mt + 1].z : Ar[2 * mt + 1].x;
                unsigned a3 = ks ? Ar[2 * mt + 1].w : Ar[2 * mt + 1].y;
                #pragma unroll
                for (int jp = 0; jp < 2; jp++) {
                    mma_f16(acc[mt][2 * jp][0], acc[mt][2 * jp][1],
                            acc[mt][2 * jp][2], acc[mt][2 * jp][3],
                            a0, a1, a2, a3, Bq[jp].x, Bq[jp].y);
                    mma_f16(acc[mt][2 * jp + 1][0], acc[mt][2 * jp + 1][1],
                            acc[mt][2 * jp + 1][2], acc[mt][2 * jp + 1][3],
                            a0, a1, a2, a3, Bq[jp].z, Bq[jp].w);
                }
            }
        }
    }

    #pragma unroll
    for (int j = 0; j < 4; j++) {
        int oc = ochalf * 32 + j * 8 + 2 * t;
        float2 bb = *(const float2*)&b2[oc];
        #pragma unroll
        for (int mt = 0; mt < 4; mt++) {
            int plo = prow[mt * 2], phi = prow[mt * 2 + 1];
            if (plo < 961)
                *(unsigned*)&g_c2h[((size_t)b * 961 + plo) * 64 + oc] =
                    packh2(fmaxf(acc[mt][j][0] + bb.x, 0.f),
                           fmaxf(acc[mt][j][1] + bb.y, 0.f));
            if (phi < 961)
                *(unsigned*)&g_c2h[((size_t)b * 961 + phi) * 64 + oc] =
                    packh2(fmaxf(acc[mt][j][2] + bb.x, 0.f),
                           fmaxf(acc[mt][j][3] + bb.y, 0.f));
        }
    }
}

// ---------------------------------------------------------------------------
// Launch 5: pool2 -> packed padded pairs (conv3 layout, 17x17, stride 32).
// ---------------------------------------------------------------------------
__global__ void k_pool2() {
    int idx = blockIdx.x * 256 + threadIdx.x;     // 512*225*32
    int q = idx & 31; int t2 = idx >> 5;
    int p = t2 % 225; int b = t2 / 225;
    int py = p / 15, px = p - py * 15;
    const __half2* ip = (const __half2*)(g_c2h + ((size_t)(b * 31 + 2 * py) * 31 + 2 * px) * 64 + 2 * q);
    __half2 m = __hmax2(__hmax2(ip[0], ip[32]), __hmax2(ip[31 * 32], ip[32 * 32]));
    int pos = (q & 16) + 4 * (q & 3) + ((q >> 2) & 3);
    g_p2p[b * P2_STRIDE + ((py + 1) * 17 + px + 1) * 32 + pos] = *(unsigned*)&m;
}

// ---------------------------------------------------------------------------
// Launch 6: conv3 fp16 mma. grid (512, 2 oc-halves), 8 warps x 32 px x 64 oc.
// 2 blocks/SM. sIn padded 17x17 stride 32.
// ---------------------------------------------------------------------------
#define C3_SINU  P2_STRIDE                          // 9248 uints
#define C3_WFU   (9 * 2048)                         // 18432 uints
#define C3_SMEM  ((C3_SINU + C3_WFU) * 4)           // 110720 B

__global__ __launch_bounds__(256, 2) void k_conv3_mma(const float* __restrict__ b3) {
    unsigned* sIn = smem_u;
    unsigned* wf  = smem_u + C3_SINU;
    int b = blockIdx.x;
    int ochalf = blockIdx.y;
    int tid = threadIdx.x;
    int warp = tid >> 5, lane = tid & 31;
    int g = lane >> 2, t = lane & 3;

    {
        const uint4* ss = (const uint4*)(g_p2p + (size_t)b * P2_STRIDE);
        uint4* sd = (uint4*)sIn;
        for (int i = tid; i < C3_SINU / 4; i += 256) sd[i] = ss[i];
        const uint4* ws = (const uint4*)(g_w3f + ochalf * C3_WFU);
        uint4* wd = (uint4*)wf;
        for (int i = tid; i < C3_WFU / 4; i += 256) wd[i] = ws[i];
    }
    __syncthreads();

    int p0 = warp * 32;
    int prow[4], abase[4];
    #pragma unroll
    for (int mt = 0; mt < 2; mt++)
        #pragma unroll
        for (int h = 0; h < 2; h++) {
            int i = mt * 2 + h;
            int p = p0 + mt * 16 + g + h * 8;
            int py = p / 15, px = p - py * 15;
            prow[i] = p;
            abase[i] = (py * 17 + px) * 32 + 4 * t;
        }

    float acc[2][8][4];
    #pragma unroll
    for (int mt = 0; mt < 2; mt++)
        #pragma unroll
        for (int j = 0; j < 8; j++)
            #pragma unroll
            for (int q = 0; q < 4; q++) acc[mt][j][q] = 0.f;

    #pragma unroll 1
    for (int tap = 0; tap < 9; tap++) {
        const unsigned* cur = wf + tap * 2048;
        int ky = tap / 3, kx = tap - ky * 3;
        int toff = (ky * 17 + kx) * 32;
        #pragma unroll
        for (int kk = 0; kk < 2; kk++) {
            uint4 Ar[4];
            #pragma unroll
            for (int i = 0; i < 4; i++)
                Ar[i] = *(const uint4*)&sIn[abase[i] + toff + 16 * kk];
            #pragma unroll
            for (int ks2 = 0; ks2 < 2; ks2++) {
                int ks = kk * 2 + ks2;
                uint4 Bq[4];
                #pragma unroll
                for (int jp = 0; jp < 4; jp++)
                    Bq[jp] = *(const uint4*)&cur[((ks * 4 + jp) * 32 + lane) * 4];
                #pragma unroll
                for (int mt = 0; mt < 2; mt++) {
                    unsigned a0 = ks2 ? Ar[2 * mt].z     : Ar[2 * mt].x;
                    unsigned a2 = ks2 ? Ar[2 * mt].w     : Ar[2 * mt].y;
                    unsigned a1 = ks2 ? Ar[2 * mt + 1].z : Ar[2 * mt + 1].x;
                    unsigned a3 = ks2 ? Ar[2 * mt + 1].w : Ar[2 * mt + 1].y;
                    #pragma unroll
                    for (int jp = 0; jp < 4; jp++) {
                        mma_f16(acc[mt][2 * jp][0], acc[mt][2 * jp][1],
                                acc[mt][2 * jp][2], acc[mt][2 * jp][3],
                                a0, a1, a2, a3, Bq[jp].x, Bq[jp].y);
                        mma_f16(acc[mt][2 * jp + 1][0], acc[mt][2 * jp + 1][1],
                                acc[mt][2 * jp + 1][2], acc[mt][2 * jp + 1][3],
                                a0, a1, a2, a3, Bq[jp].z, Bq[jp].w);
                    }
                }
            }
        }
    }

    #pragma unroll
    for (int j = 0; j < 8; j++) {
        int oc = ochalf * 64 + j * 8 + 2 * t;
        float2 bb = *(const float2*)&b3[oc];
        #pragma unroll
        for (int mt = 0; mt < 2; mt++) {
            int plo = prow[mt * 2], phi = prow[mt * 2 + 1];
            if (plo < 225)
                *(unsigned*)&g_c3h[((size_t)b * 225 + plo) * 128 + oc] =
                    packh2(fmaxf(acc[mt][j][0] + bb.x, 0.f),
                           fmaxf(acc[mt][j][1] + bb.y, 0.f));
            if (phi < 225)
                *(unsigned*)&g_c3h[((size_t)b * 225 + phi) * 128 + oc] =
                    packh2(fmaxf(acc[mt][j][2] + bb.x, 0.f),
                           fmaxf(acc[mt][j][3] + bb.y, 0.f));
        }
    }
}

// ---------------------------------------------------------------------------
// Launch 7: pool3 (2x2 s2) + mean.  Launch 8: FC.
// ---------------------------------------------------------------------------
__global__ void k_avg() {
    int idx = blockIdx.x * 256 + threadIdx.x;   // 512*64 pairs
    int q = idx & 63; int b = idx >> 6;
    const __half2* ip = (const __half2*)(g_c3h + (size_t)b * 225 * 128 + 2 * q);
    float s0 = 0.f, s1 = 0.f;
    #pragma unroll
    for (int py = 0; py < 7; py++)
        #pragma unroll
        for (int px = 0; px < 7; px++) {
            const __half2* w = ip + ((2 * py) * 15 + 2 * px) * 64;
            __half2 m = __hmax2(__hmax2(w[0], w[64]), __hmax2(w[15 * 64], w[16 * 64]));
            float2 f = __half22float2(m);
            s0 += f.x; s1 += f.y;
        }
    g_avg[b * 128 + 2 * q]     = s0 * (1.f / 49.f);
    g_avg[b * 128 + 2 * q + 1] = s1 * (1.f / 49.f);
}

__global__ void k_fc(const float* __restrict__ fw1, const float* __restrict__ fb1,
                     const float* __restrict__ fw2, const float* __restrict__ fb2,
                     float* __restrict__ out) {
    int b = blockIdx.x;
    int tid = threadIdx.x;
    __shared__ float sa[128], sh[128];
    sa[tid] = g_avg[b * 128 + tid];
    __syncthreads();
    float s = fb1[tid];
    const float* wr = fw1 + tid * 128;
    #pragma unroll 8
    for (int j = 0; j < 128; j++) s += wr[j] * sa[j];
    sh[tid] = s > 0.f ? s : 0.f;
    __syncthreads();
    if (tid < 5) {
        float o = fb2[tid];
        const float* wr2 = fw2 + tid * 128;
        #pragma unroll 8
        for (int j = 0; j < 128; j++) o += wr2[j] * sh[j];
        out[b * 5 + tid] = o;
    }
}

// ---------------------------------------------------------------------------
extern "C" void kernel_launch(void* const* d_in, const int* in_sizes, int n_in,
                              void* d_out, int out_size) {
    const int*   x   = (const int*)  d_in[0];
    const float* w1  = (const float*)d_in[1];
    const float* b1  = (const float*)d_in[2];
    const float* w2  = (const float*)d_in[3];
    const float* b2  = (const float*)d_in[4];
    const float* w3  = (const float*)d_in[5];
    const float* b3  = (const float*)d_in[6];
    const float* fw1 = (const float*)d_in[7];
    const float* fb1 = (const float*)d_in[8];
    const float* fw2 = (const float*)d_in[9];
    const float* fb2 = (const float*)d_in[10];
    float* out = (float*)d_out;

    cudaFuncSetAttribute(k_conv2_mma, cudaFuncAttributeMaxDynamicSharedMemorySize, C2_SMEM);
    cudaFuncSetAttribute(k_conv3_mma, cudaFuncAttributeMaxDynamicSharedMemorySize, C3_SMEM);

    k_setup<<<L1_GRID, 256>>>(x, w2, w3);                       // 1
    k_scatter1<<<NIMG, 256>>>(w1);                              // 2
    k_pool1<<<(NB * 961 * 16) / 256, 256>>>(b1);                // 3
    k_conv2_mma<<<dim3(NB, 2, 2), 256, C2_SMEM>>>(b2);          // 4 <- profiled
    k_pool2<<<(NB * 225 * 32) / 256, 256>>>();                  // 5
    k_conv3_mma<<<dim3(NB, 2), 256, C3_SMEM>>>(b3);             // 6
    k_avg<<<(NB * 64) / 256, 256>>>();                          // 7
    k_fc<<<NB, 128>>>(fw1, fb1, fw2, fb2, out);                 // 8
}

// round 14
// speedup vs baseline: 1.9808x; 1.0634x over previous
#include <cuda_runtime.h>
#include <cuda_bf16.h>
#include <cuda_fp16.h>
#include <math_constants.h>

// ---------------------------------------------------------------------------
//   x -> nonzero list ; conv1 sparse scatter into c1 f32 NHWC (global)
//   pool1 3x3 s2 + bias + relu -> g_p1p packed padded fp16 (conv2 sIn layout)
//   conv2 5x5 32->64 fp16 mma + FUSED pool2 -> writes g_p2p directly
//   conv3 3x3 64->128 fp16 mma + FUSED pool3+mean -> writes g_avg directly
//   fc 128->128 relu -> 5
//
// Packed pair layouts (uint = f16x2 of channels 2P,2P+1):
//  conv2 input (32ch, 16 pairs/px, stride 16): pos(P) = 4*(P&3) + (P>>2)
//    -> thread t LDS.128 at 4t gives pairs {t,t+4,8+t,12+t} (k-chunks 0,1).
//  conv3 input (64ch, stride 32): pos(P) = (P&16) + 4*(P&3) + ((P>>2)&3)
//  B weights: uint4 per lane = {B[2jp].b0,b1, B[2jp+1].b0,b1}, per oc-half.
// Halo borders of g_p1p/g_p2p are never written (zero-init persists).
// Pool splits never cross block boundaries: pool2 py<=7 uses rows<=15 (yhalf0),
// py>=8 uses rows>=16 (yhalf1); conv3 block owns all 225 px of its 64 oc.
//
// mma.m16n8k16.f16 (g=lane>>2, t=lane&3): A a0=(g,2t:2t+1) a1=(g+8,..)
//   a2=(g,2t+8:2t+9) a3=(g+8,..); B b0=B[2t:2t+1][g] b1=B[2t+8:2t+9][g];
//   C c0=(g,2t) c1=(g,2t+1) c2=(g+8,2t) c3=(g+8,2t+1)
// ---------------------------------------------------------------------------

#define NB 512
#define NIMG (NB * 4)

#define P1_STRIDE (35 * 35 * 16)        // 19600 uints per image
#define P2_STRIDE (17 * 17 * 32)        // 9248 uints per image

__device__ float  g_c1 [NB * 64 * 64 * 32];
__device__ __align__(16) unsigned g_p1p[NB * P1_STRIDE];
__device__ __align__(16) unsigned g_p2p[NB * P2_STRIDE];
__device__ float  g_avg[NB * 128];
__device__ int            g_nzcnt [NIMG];
__device__ unsigned short g_nzlist[NIMG * 256];
__device__ __align__(16) unsigned g_w2f[2 * 25 * 512];   // [ochalf][tap][512]
__device__ __align__(16) unsigned g_w3f[2 * 9 * 2048];   // [ochalf][tap][2048]

__device__ __forceinline__ unsigned packh2(float a, float b) {
    __half2 h = __floats2half2_rn(a, b);
    return *(unsigned*)&h;
}

__device__ __forceinline__ void mma_f16(float& c0, float& c1, float& c2, float& c3,
                                        unsigned a0, unsigned a1, unsigned a2, unsigned a3,
                                        unsigned b0, unsigned b1) {
    asm volatile("mma.sync.aligned.m16n8k16.row.col.f32.f16.f16.f32 "
                 "{%0,%1,%2,%3},{%4,%5,%6,%7},{%8,%9},{%0,%1,%2,%3};"
                 : "+f"(c0), "+f"(c1), "+f"(c2), "+f"(c3)
                 : "r"(a0), "r"(a1), "r"(a2), "r"(a3), "r"(b0), "r"(b1));
}

// ---------------------------------------------------------------------------
// Launch 1: raster (blocks < NIMG) + zero c1 + weight prep, one grid.
// ---------------------------------------------------------------------------
#define ZB1 65536
#define PB  ((25600 + 36864 + 255) / 256)
#define L1_GRID (NIMG + ZB1 + PB)

__global__ void k_setup(const int* __restrict__ x,
                        const float* __restrict__ w2, const float* __restrict__ w3) {
    int bi = blockIdx.x;
    int tid = threadIdx.x;
    if (bi >= NIMG) {
        int zb = bi - NIMG;
        if (zb < ZB1) {
            ((float4*)g_c1)[zb * 256 + tid] = make_float4(0.f, 0.f, 0.f, 0.f);
        } else {
            int i = (zb - ZB1) * 256 + tid;
            if (i < 25600) {
                int half = i / 12800; int r = i - half * 12800;
                int tap = r >> 9; int i2 = r & 511;
                int c = i2 & 3, ln = (i2 >> 2) & 31, jp = (i2 >> 7) & 1, ks = (i2 >> 8) & 1;
                int h = c & 1, jpar = c >> 1;
                int tt = ln & 3, gg = ln >> 2;
                int k = ks * 16 + 2 * tt + 8 * h;
                int n = half * 32 + (2 * jp + jpar) * 8 + gg;
                g_w2f[i] = packh2(w2[n * 800 + k * 25 + tap],
                                  w2[n * 800 + (k + 1) * 25 + tap]);
            } else if (i < 25600 + 36864) {
                int ii = i - 25600;
                int half = ii / 18432; int r = ii - half * 18432;
                int tap = r >> 11; int i2 = r & 2047;
                int c = i2 & 3, ln = (i2 >> 2) & 31, jp = (i2 >> 7) & 3, ks = (i2 >> 9) & 3;
                int h = c & 1, jpar = c >> 1;
                int tt = ln & 3, gg = ln >> 2;
                int k = ks * 16 + 2 * tt + 8 * h;
                int oc = half * 64 + (2 * jp + jpar) * 8 + gg;
                g_w3f[ii] = packh2(w3[oc * 576 + k * 9 + tap],
                                   w3[oc * 576 + (k + 1) * 9 + tap]);
            }
        }
        return;
    }
    int img = bi;
    __shared__ int ax[9], ay[9];
    __shared__ int sdX, sloX, shiX, sloY, shiY;
    __shared__ int sCnt;
    __shared__ unsigned short sList[256];
    if (tid < 9) {
        int vx = x[img * 20 + tid * 2 + 0];
        int vy = x[img * 20 + tid * 2 + 1];
        ax[tid] = ((vx + 64) % 127 + 127) % 127;
        ay[tid] = ((64 - vy) % 127 + 127) % 127;
    }
    if (tid == 9) {
        int vx = x[img * 20 + 18];
        int vy = x[img * 20 + 19];
        int dX = 64 + vx, dY = 64 - vy;
        sdX = dX;
        sloX = (dX >= 64) ? 64 : dX + 1;
        shiX = (dX >= 64) ? dX - 1 : 64;
        sloY = (dY >= 64) ? 64 : dY + 1;
        shiY = (dY >= 64) ? dY - 1 : 64;
    }
    if (tid == 10) sCnt = 0;
    __syncthreads();
    for (int p = tid; p < 16384; p += blockDim.x) {
        int y = p >> 7, xx = p & 127;
        float val = 0.f;
        if (y == 64 && xx >= sloX && xx <= shiX) val = -1.f;
        if (xx == sdX && y >= sloY && y <= shiY) val = -1.f;
        if (y >= 63 && y <= 65 && xx >= 63 && xx <= 65)
            val = (y == 64 && xx == 64) ? 1.f : 0.5f;
        #pragma unroll
        for (int k = 0; k < 9; k++) {
            int dy = y - ay[k], dx = xx - ax[k];
            if (dy >= -1 && dy <= 1 && dx >= -1 && dx <= 1)
                val = (dy == 0 && dx == 0) ? 1.f : 0.5f;
        }
        if (val != 0.f) {
            int pos = atomicAdd(&sCnt, 1);
            if (pos < 256) {
                int code = (val == 0.5f) ? 0 : ((val == 1.f) ? 1 : 2);
                sList[pos] = (unsigned short)(p | (code << 14));
            }
        }
    }
    __syncthreads();
    int cnt = sCnt < 256 ? sCnt : 256;
    if (tid == 0) g_nzcnt[img] = cnt;
    for (int i = tid; i < cnt; i += blockDim.x)
        g_nzlist[img * 256 + i] = sList[i];
}

// ---------------------------------------------------------------------------
// Launch 2: sparse conv1 scatter (f32 atomics into NHWC c1).
// ---------------------------------------------------------------------------
__global__ void k_scatter1(const float* __restrict__ w1) {
    int img = blockIdx.x;
    int b = img >> 2, ci = img & 3;
    __shared__ float sW[49 * 32];
    __shared__ unsigned short sList[256];
    __shared__ int sCnt;
    int tid = threadIdx.x;
    for (int i = tid; i < 49 * 32; i += 256) {
        int oc = i & 31; int r = i >> 5;
        int ky = r / 7, kx = r % 7;
        sW[i] = w1[((oc * 4 + ci) * 7 + ky) * 7 + kx];
    }
    if (tid == 0) sCnt = g_nzcnt[img];
    __syncthreads();
    int cnt = sCnt;
    for (int i = tid; i < cnt; i += 256) sList[i] = g_nzlist[img * 256 + i];
    __syncthreads();
    int warp = tid >> 5, lane = tid & 31;
    for (int e = warp; e < cnt; e += 8) {
        int ent = sList[e];
        int p = ent & 16383, code = ent >> 14;
        float v = (code == 0) ? 0.5f : ((code == 1) ? 1.0f : -1.0f);
        int iy = p >> 7, ix = p & 127;
        #pragma unroll
        for (int ky = 0; ky < 7; ky++) {
            int t = iy + 3 - ky;
            if (t < 0 || t >= 128 || (t & 1)) continue;
            int oy = t >> 1;
            #pragma unroll
            for (int kx = 0; kx < 7; kx++) {
                int u = ix + 3 - kx;
                if (u < 0 || u >= 128 || (u & 1)) continue;
                int ox = u >> 1;
                atomicAdd(&g_c1[((b * 64 + oy) * 64 + ox) * 32 + lane],
                          v * sW[(ky * 7 + kx) * 32 + lane]);
            }
        }
    }
}

// ---------------------------------------------------------------------------
// Launch 3: pool1 -> packed padded fp16 (conv2 layout). pos = 4*(u&3)+(u>>2).
// ---------------------------------------------------------------------------
__global__ void k_pool1(const float* __restrict__ b1) {
    int idx = blockIdx.x * 256 + threadIdx.x;
    int u = idx & 15; int t2 = idx >> 4;
    int p = t2 % 961; int b = t2 / 961;
    int py = p / 31, px = p - py * 31;
    int oc0 = 2 * u;
    const float* ip = g_c1 + ((size_t)(b * 64 + 2 * py) * 64 + 2 * px) * 32 + oc0;
    float m0 = -CUDART_INF_F, m1 = -CUDART_INF_F;
    #pragma unroll
    for (int dy = 0; dy < 3; dy++)
        #pragma unroll
        for (int dx = 0; dx < 3; dx++) {
            float2 v = *(const float2*)&ip[(dy * 64 + dx) * 32];
            m0 = fmaxf(m0, v.x); m1 = fmaxf(m1, v.y);
        }
    float2 bb = *(const float2*)&b1[oc0];
    m0 = fmaxf(m0 + bb.x, 0.f); m1 = fmaxf(m1 + bb.y, 0.f);
    int pos = 4 * (u & 3) + (u >> 2);
    g_p1p[b * P1_STRIDE + ((py + 2) * 35 + px + 2) * 16 + pos] = packh2(m0, m1);
}

// ---------------------------------------------------------------------------
// Launch 4 (PROFILED): conv2 fp16 mma + fused pool2.
// grid (512, 2 row-halves, 2 oc-halves). 8 warps x 64 px x 32 oc. 2 blk/SM.
// Epilogue: stash tile in smem (reuse sIn), pool 2x2 s2, write g_p2p.
// ---------------------------------------------------------------------------
#define C2_SINU  (21 * 35 * 16)                     // 11760 uints
#define C2_WFU   (25 * 512)                         // 12800 uints
#define C2_SMEM  ((C2_SINU + C2_WFU) * 4)           // 98240 B

extern __shared__ unsigned smem_u[];

__global__ __launch_bounds__(256, 2) void k_conv2_mma(const float* __restrict__ b2) {
    unsigned* sIn = smem_u;
    unsigned* wf  = smem_u + C2_SINU;
    int b = blockIdx.x;
    int y0 = blockIdx.y * 16;
    int ochalf = blockIdx.z;
    int tid = threadIdx.x;
    int warp = tid >> 5, lane = tid & 31;
    int g = lane >> 2, t = lane & 3;

    {
        const uint4* ss = (const uint4*)(g_p1p + (size_t)b * P1_STRIDE + y0 * 35 * 16);
        uint4* sd = (uint4*)sIn;
        int navail = (35 - y0) * 35 * 4;
        for (int i = tid; i < C2_SINU / 4; i += 256)
            sd[i] = (i < navail) ? ss[i] : make_uint4(0u, 0u, 0u, 0u);
        const uint4* ws = (const uint4*)(g_w2f + ochalf * C2_WFU);
        uint4* wd = (uint4*)wf;
        for (int i = tid; i < C2_WFU / 4; i += 256) wd[i] = ws[i];
    }
    __syncthreads();

    int p0 = warp * 64;
    int plr[8], plx[8], abase[8];
    #pragma unroll
    for (int mt = 0; mt < 4; mt++)
        #pragma unroll
        for (int h = 0; h < 2; h++) {
            int i = mt * 2 + h;
            int p = p0 + mt * 16 + g + h * 8;       // 0..511 local
            int pyl = p / 31, px = p - pyl * 31;
            plr[i] = pyl; plx[i] = px;
            abase[i] = (pyl * 35 + px) * 16 + 4 * t;
        }

    float acc[4][4][4];
    #pragma unroll
    for (int mt = 0; mt < 4; mt++)
        #pragma unroll
        for (int j = 0; j < 4; j++)
            #pragma unroll
            for (int q = 0; q < 4; q++) acc[mt][j][q] = 0.f;

    #pragma unroll 1
    for (int tap = 0; tap < 25; tap++) {
        const unsigned* cur = wf + tap * 512;
        int ky = tap / 5, kx = tap - ky * 5;
        int toff = (ky * 35 + kx) * 16;
        uint4 Ar[8];
        #pragma unroll
        for (int i = 0; i < 8; i++)
            Ar[i] = *(const uint4*)&sIn[abase[i] + toff];
        #pragma unroll
        for (int ks = 0; ks < 2; ks++) {
            uint4 Bq[2];
            #pragma unroll
            for (int jp = 0; jp < 2; jp++)
                Bq[jp] = *(const uint4*)&cur[((ks * 2 + jp) * 32 + lane) * 4];
            #pragma unroll
            for (int mt = 0; mt < 4; mt++) {
                unsigned a0 = ks ? Ar[2 * mt].z     : Ar[2 * mt].x;
                unsigned a2 = ks ? Ar[2 * mt].w     : Ar[2 * mt].y;
                unsigned a1 = ks ? Ar[2 * mt + 1].z : Ar[2 * mt + 1].x;
                unsigned a3 = ks ? Ar[2 * mt + 1].w : Ar[2 * mt + 1].y;
                #pragma unroll
                for (int jp = 0; jp < 2; jp++) {
                    mma_f16(acc[mt][2 * jp][0], acc[mt][2 * jp][1],
                            acc[mt][2 * jp][2], acc[mt][2 * jp][3],
                            a0, a1, a2, a3, Bq[jp].x, Bq[jp].y);
                    mma_f16(acc[mt][2 * jp + 1][0], acc[mt][2 * jp + 1][1],
                            acc[mt][2 * jp + 1][2], acc[mt][2 * jp + 1][3],
                            a0, a1, a2, a3, Bq[jp].z, Bq[jp].w);
                }
            }
        }
    }

    // ---- Fused epilogue: stash c2 tile in smem, pool 2x2 s2 -> g_p2p ----
    __syncthreads();                                // done with sIn
    unsigned* sc2 = smem_u;                         // [row16][px31][pair16]
    int rowlim = (31 - y0 < 16) ? (31 - y0) : 16;   // valid local rows
    #pragma unroll
    for (int j = 0; j < 4; j++) {
        int jj = j * 4 + t;                         // local oc pair 0..15
        float2 bb = *(const float2*)&b2[ochalf * 32 + 2 * jj];
        #pragma unroll
        for (int mt = 0; mt < 4; mt++) {
            int ilo = mt * 2, ihi = mt * 2 + 1;
            if (plr[ilo] < rowlim)
                sc2[(plr[ilo] * 31 + plx[ilo]) * 16 + jj] =
                    packh2(fmaxf(acc[mt][j][0] + bb.x, 0.f),
                           fmaxf(acc[mt][j][1] + bb.y, 0.f));
            if (plr[ihi] < rowlim)
                sc2[(plr[ihi] * 31 + plx[ihi]) * 16 + jj] =
                    packh2(fmaxf(acc[mt][j][2] + bb.x, 0.f),
                           fmaxf(acc[mt][j][3] + bb.y, 0.f));
        }
    }
    __syncthreads();
    int npool = (y0 == 0) ? 8 : 7;
    for (int i = tid; i < npool * 15 * 16; i += 256) {
        int jj = i & 15; int r = i >> 4;
        int px = r % 15; int pyl2 = r / 15;
        const __half2* s = (const __half2*)&sc2[((2 * pyl2) * 31 + 2 * px) * 16 + jj];
        __half2 m = __hmax2(__hmax2(s[0], s[16]), __hmax2(s[31 * 16], s[31 * 16 + 16]));
        int pyp = (y0 == 0) ? pyl2 : (8 + pyl2);
        int pos = ochalf * 16 + 4 * (jj & 3) + ((jj >> 2) & 3);
        g_p2p[b * P2_STRIDE + ((pyp + 1) * 17 + px + 1) * 32 + pos] = *(unsigned*)&m;
    }
}

// ---------------------------------------------------------------------------
// Launch 5: conv3 fp16 mma + fused pool3+mean. grid (512, 2 oc-halves),
// 8 warps x 32 px x 64 oc. 2 blocks/SM. Writes g_avg directly.
// ---------------------------------------------------------------------------
#define C3_SINU  P2_STRIDE                          // 9248 uints
#define C3_WFU   (9 * 2048)                         // 18432 uints
#define C3_SMEM  ((C3_SINU + C3_WFU) * 4)           // 110720 B

__global__ __launch_bounds__(256, 2) void k_conv3_mma(const float* __restrict__ b3) {
    unsigned* sIn = smem_u;
    unsigned* wf  = smem_u + C3_SINU;
    int b = blockIdx.x;
    int ochalf = blockIdx.y;
    int tid = threadIdx.x;
    int warp = tid >> 5, lane = tid & 31;
    int g = lane >> 2, t = lane & 3;

    {
        const uint4* ss = (const uint4*)(g_p2p + (size_t)b * P2_STRIDE);
        uint4* sd = (uint4*)sIn;
        for (int i = tid; i < C3_SINU / 4; i += 256) sd[i] = ss[i];
        const uint4* ws = (const uint4*)(g_w3f + ochalf * C3_WFU);
        uint4* wd = (uint4*)wf;
        for (int i = tid; i < C3_WFU / 4; i += 256) wd[i] = ws[i];
    }
    __syncthreads();

    int p0 = warp * 32;
    int prow[4], abase[4];
    #pragma unroll
    for (int mt = 0; mt < 2; mt++)
        #pragma unroll
        for (int h = 0; h < 2; h++) {
            int i = mt * 2 + h;
            int p = p0 + mt * 16 + g + h * 8;
            int py = p / 15, px = p - py * 15;
            prow[i] = p;
            abase[i] = (py * 17 + px) * 32 + 4 * t;
        }

    float acc[2][8][4];
    #pragma unroll
    for (int mt = 0; mt < 2; mt++)
        #pragma unroll
        for (int j = 0; j < 8; j++)
            #pragma unroll
            for (int q = 0; q < 4; q++) acc[mt][j][q] = 0.f;

    #pragma unroll 1
    for (int tap = 0; tap < 9; tap++) {
        const unsigned* cur = wf + tap * 2048;
        int ky = tap / 3, kx = tap - ky * 3;
        int toff = (ky * 17 + kx) * 32;
        #pragma unroll
        for (int kk = 0; kk < 2; kk++) {
            uint4 Ar[4];
            #pragma unroll
            for (int i = 0; i < 4; i++)
                Ar[i] = *(const uint4*)&sIn[abase[i] + toff + 16 * kk];
            #pragma unroll
            for (int ks2 = 0; ks2 < 2; ks2++) {
                int ks = kk * 2 + ks2;
                uint4 Bq[4];
                #pragma unroll
                for (int jp = 0; jp < 4; jp++)
                    Bq[jp] = *(const uint4*)&cur[((ks * 4 + jp) * 32 + lane) * 4];
                #pragma unroll
                for (int mt = 0; mt < 2; mt++) {
                    unsigned a0 = ks2 ? Ar[2 * mt].z     : Ar[2 * mt].x;
                    unsigned a2 = ks2 ? Ar[2 * mt].w     : Ar[2 * mt].y;
                    unsigned a1 = ks2 ? Ar[2 * mt + 1].z : Ar[2 * mt + 1].x;
                    unsigned a3 = ks2 ? Ar[2 * mt + 1].w : Ar[2 * mt + 1].y;
                    #pragma unroll
                    for (int jp = 0; jp < 4; jp++) {
                        mma_f16(acc[mt][2 * jp][0], acc[mt][2 * jp][1],
                                acc[mt][2 * jp][2], acc[mt][2 * jp][3],
                                a0, a1, a2, a3, Bq[jp].x, Bq[jp].y);
                        mma_f16(acc[mt][2 * jp + 1][0], acc[mt][2 * jp + 1][1],
                                acc[mt][2 * jp + 1][2], acc[mt][2 * jp + 1][3],
                                a0, a1, a2, a3, Bq[jp].z, Bq[jp].w);
                    }
                }
            }
        }
    }

    // ---- Fused epilogue: stash tile, pool 2x2 s2 (15->7) + mean -> g_avg ----
    __syncthreads();
    unsigned* sc3 = smem_u;                          // [225][32 pairs]
    float* sred = (float*)(smem_u + 7232);           // [7 parts][32 pairs][2]
    #pragma unroll
    for (int j = 0; j < 8; j++) {
        int jj = j * 4 + t;                          // local oc pair 0..31
        float2 bb = *(const float2*)&b3[ochalf * 64 + 2 * jj];
        #pragma unroll
        for (int mt = 0; mt < 2; mt++) {
            int plo = prow[mt * 2], phi = prow[mt * 2 + 1];
            if (plo < 225)
                sc3[plo * 32 + jj] = packh2(fmaxf(acc[mt][j][0] + bb.x, 0.f),
                                            fmaxf(acc[mt][j][1] + bb.y, 0.f));
            if (phi < 225)
                sc3[phi * 32 + jj] = packh2(fmaxf(acc[mt][j][2] + bb.x, 0.f),
                                            fmaxf(acc[mt][j][3] + bb.y, 0.f));
        }
    }
    __syncthreads();
    if (tid < 224) {
        int pair = tid & 31, py = tid >> 5;          // py 0..6
        float s0 = 0.f, s1 = 0.f;
        #pragma unroll
        for (int px = 0; px < 7; px++) {
            const __half2* s = (const __half2*)&sc3[((2 * py) * 15 + 2 * px) * 32 + pair];
            __half2 m = __hmax2(__hmax2(s[0], s[32]), __hmax2(s[15 * 32], s[15 * 32 + 32]));
            float2 f = __half22float2(m);
            s0 += f.x; s1 += f.y;
        }
        sred[(py * 32 + pair) * 2]     = s0;
        sred[(py * 32 + pair) * 2 + 1] = s1;
    }
    __syncthreads();
    if (tid < 32) {
        float s0 = 0.f, s1 = 0.f;
        #pragma unroll
        for (int py = 0; py < 7; py++) {
            s0 += sred[(py * 32 + tid) * 2];
            s1 += sred[(py * 32 + tid) * 2 + 1];
        }
        g_avg[b * 128 + ochalf * 64 + 2 * tid]     = s0 * (1.f / 49.f);
        g_avg[b * 128 + ochalf * 64 + 2 * tid + 1] = s1 * (1.f / 49.f);
    }
}

// ---------------------------------------------------------------------------
// Launch 6: FC 128 -> 128 relu -> 5
// ---------------------------------------------------------------------------
__global__ void k_fc(const float* __restrict__ fw1, const float* __restrict__ fb1,
                     const float* __restrict__ fw2, const float* __restrict__ fb2,
                     float* __restrict__ out) {
    int b = blockIdx.x;
    int tid = threadIdx.x;
    __shared__ float sa[128], sh[128];
    sa[tid] = g_avg[b * 128 + tid];
    __syncthreads();
    float s = fb1[tid];
    const float* wr = fw1 + tid * 128;
    #pragma unroll 8
    for (int j = 0; j < 128; j++) s += wr[j] * sa[j];
    sh[tid] = s > 0.f ? s : 0.f;
    __syncthreads();
    if (tid < 5) {
        float o = fb2[tid];
        const float* wr2 = fw2 + tid * 128;
        #pragma unroll 8
        for (int j = 0; j < 128; j++) o += wr2[j] * sh[j];
        out[b * 5 + tid] = o;
    }
}

// ---------------------------------------------------------------------------
extern "C" void kernel_launch(void* const* d_in, const int* in_sizes, int n_in,
                              void* d_out, int out_size) {
    const int*   x   = (const int*)  d_in[0];
    const float* w1  = (const float*)d_in[1];
    const float* b1  = (const float*)d_in[2];
    const float* w2  = (const float*)d_in[3];
    const float* b2  = (const float*)d_in[4];
    const float* w3  = (const float*)d_in[5];
    const float* b3  = (const float*)d_in[6];
    const float* fw1 = (const float*)d_in[7];
    const float* fb1 = (const float*)d_in[8];
    const float* fw2 = (const float*)d_in[9];
    const float* fb2 = (const float*)d_in[10];
    float* out = (float*)d_out;

    cudaFuncSetAttribute(k_conv2_mma, cudaFuncAttributeMaxDynamicSharedMemorySize, C2_SMEM);
    cudaFuncSetAttribute(k_conv3_mma, cudaFuncAttributeMaxDynamicSharedMemorySize, C3_SMEM);

    k_setup<<<L1_GRID, 256>>>(x, w2, w3);                       // 1
    k_scatter1<<<NIMG, 256>>>(w1);                              // 2
    k_pool1<<<(NB * 961 * 16) / 256, 256>>>(b1);                // 3
    k_conv2_mma<<<dim3(NB, 2, 2), 256, C2_SMEM>>>(b2);          // 4 <- profiled
    k_conv3_mma<<<dim3(NB, 2), 256, C3_SMEM>>>(b3);             // 5
    k_fc<<<NB, 128>>>(fw1, fb1, fw2, fb2, out);                 // 6
}